// round 12
// baseline (speedup 1.0000x reference)
#include <cuda_runtime.h>
#include <cuda_fp16.h>
#include <math.h>
#include <stdint.h>

#define BATCH 16
#define SEQ   1024
#define DIM   768
#define GP    49
#define ROWS  (BATCH * SEQ)      // 16384
#define QKVD  (3 * DIM)          // 2304

// ---------------- scratch (device globals) ----------------------------------
__device__ float g_gw [(size_t)ROWS * GP];
__device__ float g_S  [(size_t)BATCH * SEQ * SEQ];
__device__ float g_rmax[ROWS];
__device__ float g_rsum[ROWS];

__device__ half g_x_h   [(size_t)ROWS * DIM];
__device__ half g_qkv_h [(size_t)ROWS * QKVD];
__device__ half g_qkv_l [(size_t)ROWS * QKVD];
__device__ half g_S_h   [(size_t)BATCH * SEQ * SEQ];
__device__ half g_Vt_h  [(size_t)BATCH * DIM * SEQ];
__device__ half g_Vt_l  [(size_t)BATCH * DIM * SEQ];
__device__ half g_ov_h  [(size_t)ROWS * DIM];
__device__ half g_Wqkvt_h [(size_t)QKVD * DIM];
__device__ half g_Wqkvt_l [(size_t)QKVD * DIM];
__device__ half g_Wprojt_h[(size_t)DIM * DIM];
__device__ half g_Wprojt_l[(size_t)DIM * DIM];

// ============================ helpers =======================================
__device__ __forceinline__ uint32_t smem_u32(const void* p) {
    uint32_t a;
    asm("{ .reg .u64 t; cvta.to.shared.u64 t, %1; cvt.u32.u64 %0, t; }" : "=r"(a) : "l"(p));
    return a;
}
__device__ __forceinline__ void cp16(uint32_t s, const void* g) {
    asm volatile("cp.async.cg.shared.global [%0], [%1], 16;" :: "r"(s), "l"(g));
}
__device__ __forceinline__ void cp_commit() {
    asm volatile("cp.async.commit_group;" ::: "memory");
}
template<int N>
__device__ __forceinline__ void cp_wait() {
    asm volatile("cp.async.wait_group %0;" :: "n"(N) : "memory");
}
__device__ __forceinline__ void mma16816(float* d, const uint32_t* a, const uint32_t* b) {
    asm volatile(
        "mma.sync.aligned.m16n8k16.row.col.f32.f16.f16.f32 "
        "{%0,%1,%2,%3},{%4,%5,%6,%7},{%8,%9},{%0,%1,%2,%3};"
        : "+f"(d[0]), "+f"(d[1]), "+f"(d[2]), "+f"(d[3])
        : "r"(a[0]), "r"(a[1]), "r"(a[2]), "r"(a[3]), "r"(b[0]), "r"(b[1]));
}
__device__ __forceinline__ void ldmx4(uint32_t& r0, uint32_t& r1, uint32_t& r2, uint32_t& r3,
                                      uint32_t saddr) {
    asm volatile("ldmatrix.sync.aligned.m8n8.x4.shared.b16 {%0,%1,%2,%3}, [%4];"
                 : "=r"(r0), "=r"(r1), "=r"(r2), "=r"(r3) : "r"(saddr));
}
// swizzled byte offset within an 8KB sub-plane (128 rows x 4 chunks of 16B)
__device__ __forceinline__ uint32_t swz(int row, int ch) {
    return (uint32_t)(((row >> 1) << 7) |
           (((((row & 1) << 2) + ch) ^ ((row >> 1) & 7)) << 4));
}
// 16KB plane = two 8KB sub-planes (k halves); ch8 in 0..7 selects 16B column
__device__ __forceinline__ uint32_t swz64(int row, int ch8) {
    return (uint32_t)((ch8 >> 2) * 8192u) + swz(row, ch8 & 3);
}

// ============== fp16-pair mma.sync GEMM: C = alpha*Ah*(Bh+Bl) (+bias) =======
// 2-pass split (err ~1.9e-4 per GEMM). 128x128 tile, 256 thr.
// K-chunk 64, double-buffered (2 stages x 48KB), 3 planes (A_h, B_h, B_l).
#define PLANE_B  16384u
#define STAGE_B  49152u
#define GSMEM    (2 * STAGE_B)

template<bool WF32, bool WHI, bool WLO, bool BIAS>
__global__ void __launch_bounds__(256, 2) gemm_mma(
    const half* __restrict__ Ah, int lda, long long strA,
    const half* __restrict__ Bh, const half* __restrict__ Bl, int ldb, long long strB,
    float* __restrict__ C, half* __restrict__ Ch, half* __restrict__ Cl,
    int ldc, long long strC, const float* __restrict__ bias, int K, float alpha)
{
    extern __shared__ __align__(16) char smraw[];
    const uint32_t sb = smem_u32(smraw);
    const int tid  = threadIdx.x;
    const int lane = tid & 31;
    const int w    = tid >> 5;
    const int wm   = w & 1;
    const int wn   = w >> 1;
    const int m0 = blockIdx.y * 128, n0 = blockIdx.x * 128;

    const half* Abh = Ah + (long long)blockIdx.z * strA + (long long)m0 * lda;
    const half* Bbh = Bh + (long long)blockIdx.z * strB + (long long)n0 * ldb;
    const half* Bbl = Bl + (long long)blockIdx.z * strB + (long long)n0 * ldb;

    float acc[4][4][4];
#pragma unroll
    for (int i = 0; i < 4; i++)
#pragma unroll
        for (int j = 0; j < 4; j++)
#pragma unroll
            for (int r = 0; r < 4; r++) acc[i][j][r] = 0.f;

    const int nch = K >> 6;     // K-chunks of 64

    // 12 x cp.async(16B)/thread per chunk: planes A_h, B_h, B_l (16KB each)
    auto issue = [&](int k0, int stg) {
        const uint32_t base = sb + (uint32_t)stg * STAGE_B;
#pragma unroll
        for (int i = 0; i < 12; i++) {
            const int plane = i >> 2;
            const int cid = ((i & 3) << 8) + tid;    // 0..1023
            const int row = cid >> 3;
            const int ch8 = cid & 7;
            const uint32_t so = base + (uint32_t)plane * PLANE_B + swz64(row, ch8);
            const half* gp;
            if      (plane == 0) gp = Abh + (long long)row * lda + k0 + ch8 * 8;
            else if (plane == 1) gp = Bbh + (long long)row * ldb + k0 + ch8 * 8;
            else                 gp = Bbl + (long long)row * ldb + k0 + ch8 * 8;
            cp16(so, gp);
        }
        cp_commit();
    };

    issue(0, 0);

    const int rowl = lane & 15;
    const int cb   = lane >> 4;

    for (int c = 0; c < nch; ++c) {
        cp_wait<0>();
        __syncthreads();
        if (c + 1 < nch) issue((c + 1) << 6, (c + 1) & 1);

        const uint32_t stA_h = sb + (uint32_t)(c & 1) * STAGE_B;
        const uint32_t stB_h = stA_h + PLANE_B;
        const uint32_t stB_l = stA_h + 2 * PLANE_B;

#pragma unroll
        for (int ks = 0; ks < 4; ks++) {
            const int ch8 = 2 * ks + cb;
            uint32_t ah[4][4], bh[4][2], bl[4][2];
#pragma unroll
            for (int mi = 0; mi < 4; mi++) {
                int row = wm * 64 + mi * 16 + rowl;
                ldmx4(ah[mi][0], ah[mi][1], ah[mi][2], ah[mi][3], stA_h + swz64(row, ch8));
            }
#pragma unroll
            for (int p = 0; p < 2; p++) {
                int row = wn * 32 + p * 16 + rowl;
                ldmx4(bh[2*p][0], bh[2*p+1][0], bh[2*p][1], bh[2*p+1][1], stB_h + swz64(row, ch8));
            }
            // pass 1: Ah*Bh
#pragma unroll
            for (int mi = 0; mi < 4; mi++)
#pragma unroll
                for (int ni = 0; ni < 4; ni++)
                    mma16816(acc[mi][ni], ah[mi], bh[ni]);
            // B-lo loads: latency hides under pass-1 MMA drain
#pragma unroll
            for (int p = 0; p < 2; p++) {
                int row = wn * 32 + p * 16 + rowl;
                ldmx4(bl[2*p][0], bl[2*p+1][0], bl[2*p][1], bl[2*p+1][1], stB_l + swz64(row, ch8));
            }
            // pass 2: Ah*Bl
#pragma unroll
            for (int mi = 0; mi < 4; mi++)
#pragma unroll
                for (int ni = 0; ni < 4; ni++)
                    mma16816(acc[mi][ni], ah[mi], bl[ni]);
        }
        // no trailing barrier: next iteration's barrier precedes the issue
        // into this stage (stage (c+2)&1 == c&1 is written only after all
        // warps have passed the top-of-loop barrier, i.e. finished compute(c)).
    }

    float* Cb  = WF32 ? C  + (long long)blockIdx.z * strC : nullptr;
    half*  Chb = WHI  ? Ch + (long long)blockIdx.z * strC : nullptr;
    half*  Clb = WLO  ? Cl + (long long)blockIdx.z * strC : nullptr;
    const int r0 = m0 + wm * 64 + (lane >> 2);
    const int c0 = n0 + wn * 32 + ((lane & 3) << 1);
#pragma unroll
    for (int mi = 0; mi < 4; mi++) {
#pragma unroll
        for (int ni = 0; ni < 4; ni++) {
            int cc = c0 + ni * 8;
            float bx = 0.f, by = 0.f;
            if (BIAS) { bx = bias[cc]; by = bias[cc + 1]; }
#pragma unroll
            for (int h = 0; h < 2; h++) {
                int rr = r0 + mi * 16 + h * 8;
                float vx = acc[mi][ni][h * 2 + 0] * alpha + bx;
                float vy = acc[mi][ni][h * 2 + 1] * alpha + by;
                long long off = (long long)rr * ldc + cc;
                if (WF32) *(float2*)(Cb + off) = make_float2(vx, vy);
                if (WHI) {
                    half2 hh;
                    hh.x = __float2half_rn(vx); hh.y = __float2half_rn(vy);
                    *(half2*)(Chb + off) = hh;
                    if (WLO) {
                        half2 ll;
                        ll.x = __float2half_rn(vx - __half2float(hh.x));
                        ll.y = __float2half_rn(vy - __half2float(hh.y));
                        *(half2*)(Clb + off) = ll;
                    }
                }
            }
        }
    }
}

// ================== fp32 -> fp16 hi-only ====================================
__global__ void __launch_bounds__(256) split_hi(
    const float* __restrict__ in, half* __restrict__ oh, size_t n)
{
    size_t i = ((size_t)blockIdx.x * 256 + threadIdx.x) * 4;
    if (i >= n) return;
    float4 v = *(const float4*)(in + i);
    half2 h0, h1;
    h0.x = __float2half_rn(v.x); h0.y = __float2half_rn(v.y);
    h1.x = __float2half_rn(v.z); h1.y = __float2half_rn(v.w);
    *(half2*)(oh + i) = h0; *(half2*)(oh + i + 2) = h1;
}

// ================== transpose + split fp32 -> fp16 pair =====================
__global__ void __launch_bounds__(256) transpose_split(
    const float* __restrict__ in, half* __restrict__ oh, half* __restrict__ ol,
    int ldin, int ldout, long long sIn, long long sOut)
{
    __shared__ float t[32][33];
    const float* ib = in + (long long)blockIdx.z * sIn;
    half* obh = oh + (long long)blockIdx.z * sOut;
    half* obl = ol + (long long)blockIdx.z * sOut;
    int r0 = blockIdx.y * 32, c0 = blockIdx.x * 32;
    int x = threadIdx.x & 31, y = threadIdx.x >> 5;
#pragma unroll
    for (int j = 0; j < 32; j += 8)
        t[y + j][x] = ib[(long long)(r0 + y + j) * ldin + c0 + x];
    __syncthreads();
#pragma unroll
    for (int j = 0; j < 32; j += 8) {
        float v = t[x][y + j];
        half h = __float2half_rn(v);
        half l = __float2half_rn(v - __half2float(h));
        long long o = (long long)(c0 + y + j) * ldout + r0 + x;
        obh[o] = h; obl[o] = l;
    }
}

// ======= transpose both half planes (V -> V^T), one launch ==================
__global__ void __launch_bounds__(256) transpose_half2(
    const half* __restrict__ inh, const half* __restrict__ inl,
    half* __restrict__ outh, half* __restrict__ outl,
    int ldin, int ldout, long long sIn, long long sOut)
{
    __shared__ half t[2][32][34];
    const half* ibh = inh + (long long)blockIdx.z * sIn;
    const half* ibl = inl + (long long)blockIdx.z * sIn;
    half* obh = outh + (long long)blockIdx.z * sOut;
    half* obl = outl + (long long)blockIdx.z * sOut;
    int r0 = blockIdx.y * 32, c0 = blockIdx.x * 32;
    int x = threadIdx.x & 31, y = threadIdx.x >> 5;
#pragma unroll
    for (int j = 0; j < 32; j += 8) {
        t[0][y + j][x] = ibh[(long long)(r0 + y + j) * ldin + c0 + x];
        t[1][y + j][x] = ibl[(long long)(r0 + y + j) * ldin + c0 + x];
    }
    __syncthreads();
#pragma unroll
    for (int j = 0; j < 32; j += 8) {
        long long o = (long long)(c0 + y + j) * ldout + r0 + x;
        obh[o] = t[0][x][y + j];
        obl[o] = t[1][x][y + j];
    }
}

// ---------------- gw = softmax(q @ W_gp), 64 rows / block --------------------
__global__ void __launch_bounds__(256) gw_kernel2(
    const half* __restrict__ qh, const half* __restrict__ ql,
    const float* __restrict__ Wgp, float* __restrict__ gw)
{
    __shared__ float wt[64][52];
    __shared__ float qt[64][65];
    __shared__ float lg[64][50];
    const int row0 = blockIdx.x * 64;
    const int tid = threadIdx.x;
    const int c  = tid & 63;
    const int rq = tid >> 6;

    float acc[16];
#pragma unroll
    for (int i = 0; i < 16; i++) acc[i] = 0.f;

    for (int kc = 0; kc < DIM / 64; kc++) {
        for (int idx = tid; idx < 64 * GP; idx += 256) {
            int kk = idx / GP, cc = idx - kk * GP;
            wt[kk][cc] = Wgp[(kc * 64 + kk) * GP + cc];
        }
        for (int idx = tid; idx < 4096; idx += 256) {
            int r = idx >> 6, kk = idx & 63;
            long long o = (long long)(row0 + r) * QKVD + kc * 64 + kk;
            qt[r][kk] = __half2float(qh[o]) + __half2float(ql[o]);
        }
        __syncthreads();
        if (c < GP) {
            for (int kk = 0; kk < 64; kk++) {
                float wv = wt[kk][c];
#pragma unroll
                for (int i = 0; i < 16; i++)
                    acc[i] = fmaf(qt[rq * 16 + i][kk], wv, acc[i]);
            }
        }
        __syncthreads();
    }
    if (c < GP)
#pragma unroll
        for (int i = 0; i < 16; i++) lg[rq * 16 + i][c] = acc[i];
    __syncthreads();
    if (tid < 64) {
        float m = lg[tid][0];
        for (int j = 1; j < GP; j++) m = fmaxf(m, lg[tid][j]);
        float s = 0.f;
        float e[GP];
        for (int j = 0; j < GP; j++) { e[j] = expf(lg[tid][j] - m); s += e[j]; }
        float inv = 1.f / s;
        for (int j = 0; j < GP; j++)
            gw[(long long)(row0 + tid) * GP + j] = e[j] * inv;
    }
}

// -------- per-row max & sum(exp): warp per row, 8 rows/block -----------------
__global__ void __launch_bounds__(256) rowstats_kernel2(
    const float* __restrict__ S, float* __restrict__ rmax, float* __restrict__ rsum)
{
    const int w    = threadIdx.x >> 5;
    const int lane = threadIdx.x & 31;
    const int row  = blockIdx.x * 8 + w;
    const float4* s4 = (const float4*)(S + (long long)row * SEQ);

    float4 v[8];
    float mx = -1e30f;
#pragma unroll
    for (int i = 0; i < 8; i++) {
        v[i] = s4[i * 32 + lane];
        mx = fmaxf(mx, fmaxf(fmaxf(v[i].x, v[i].y), fmaxf(v[i].z, v[i].w)));
    }
#pragma unroll
    for (int off = 16; off > 0; off >>= 1)
        mx = fmaxf(mx, __shfl_xor_sync(0xffffffffu, mx, off));
    float sum = 0.f;
#pragma unroll
    for (int i = 0; i < 8; i++)
        sum += expf(v[i].x - mx) + expf(v[i].y - mx) + expf(v[i].z - mx) + expf(v[i].w - mx);
#pragma unroll
    for (int off = 16; off > 0; off >>= 1)
        sum += __shfl_xor_sync(0xffffffffu, sum, off);
    if (lane == 0) { rmax[row] = mx; rsum[row] = sum; }
}

// ------- W = softmax(S) * (a + (1-a)*<gw_i,gw_m>) -> fp16 hi only ------------
__global__ void __launch_bounds__(256) modulate2(
    const float* __restrict__ S, const float* __restrict__ gw,
    const float* __restrict__ rmax, const float* __restrict__ rsum,
    const float* __restrict__ alpha_p, half* __restrict__ Sh)
{
    __shared__ float gwm[128][51];
    const int b  = blockIdx.z;
    const int i0 = blockIdx.y * 64;
    const int m0 = blockIdx.x * 128;
    const int tid = threadIdx.x;

    for (int idx = tid; idx < 128 * GP; idx += 256) {
        int r = idx / GP, cc = idx - r * GP;
        gwm[r][cc] = gw[(long long)(b * SEQ + m0 + r) * GP + cc];
    }
    __syncthreads();

    const float a = 1.f / (1.f + expf(-alpha_p[0]));
    const float oma = 1.f - a;
    const int ml = tid & 63;
    const int rq = tid >> 6;

    for (int ri = 0; ri < 16; ri++) {
        const int il = ri * 4 + rq;
        const int grow = b * SEQ + i0 + il;
        const float* gp = gw + (long long)grow * GP;
        const float mi  = rmax[grow];
        const float inv = 1.f / rsum[grow];
        const float* srow = S + (long long)grow * SEQ + m0;
        float d0 = 0.f, d1 = 0.f;
#pragma unroll
        for (int cc = 0; cc < GP; cc++) {
            float g = __ldg(gp + cc);
            d0 = fmaf(g, gwm[ml][cc], d0);
            d1 = fmaf(g, gwm[ml + 64][cc], d1);
        }
        float v0 = expf(srow[ml] - mi) * inv * (a + oma * d0);
        float v1 = expf(srow[ml + 64] - mi) * inv * (a + oma * d1);
        long long o = (long long)grow * SEQ + m0;
        Sh[o + ml]      = __float2half_rn(v0);
        Sh[o + ml + 64] = __float2half_rn(v1);
    }
}

// ---------------- launcher ---------------------------------------------------
extern "C" void kernel_launch(void* const* d_in, const int* in_sizes, int n_in,
                              void* d_out, int out_size)
{
    const float* x      = (const float*)d_in[0];
    const float* W_qkv  = (const float*)d_in[1];
    const float* b_qkv  = (const float*)d_in[2];
    const float* W_proj = (const float*)d_in[3];
    const float* b_proj = (const float*)d_in[4];
    const float* W_gp   = (const float*)d_in[5];
    const float* alpha  = (const float*)d_in[6];
    float* out = (float*)d_out;

    float *gw, *S, *rmax, *rsum;
    half *x_h, *qkv_h, *qkv_l, *S_h, *Vt_h, *Vt_l, *ov_h;
    half *Wqkvt_h, *Wqkvt_l, *Wprojt_h, *Wprojt_l;
    cudaGetSymbolAddress((void**)&gw,   g_gw);
    cudaGetSymbolAddress((void**)&S,    g_S);
    cudaGetSymbolAddress((void**)&rmax, g_rmax);
    cudaGetSymbolAddress((void**)&rsum, g_rsum);
    cudaGetSymbolAddress((void**)&x_h,  g_x_h);
    cudaGetSymbolAddress((void**)&qkv_h, g_qkv_h);
    cudaGetSymbolAddress((void**)&qkv_l, g_qkv_l);
    cudaGetSymbolAddress((void**)&S_h,  g_S_h);
    cudaGetSymbolAddress((void**)&Vt_h, g_Vt_h);
    cudaGetSymbolAddress((void**)&Vt_l, g_Vt_l);
    cudaGetSymbolAddress((void**)&ov_h, g_ov_h);
    cudaGetSymbolAddress((void**)&Wqkvt_h,  g_Wqkvt_h);
    cudaGetSymbolAddress((void**)&Wqkvt_l,  g_Wqkvt_l);
    cudaGetSymbolAddress((void**)&Wprojt_h, g_Wprojt_h);
    cudaGetSymbolAddress((void**)&Wprojt_l, g_Wprojt_l);

    const float scale = (float)(1.0 / sqrt((double)DIM));
    cudaFuncSetAttribute(gemm_mma<false,true,true,true>,   cudaFuncAttributeMaxDynamicSharedMemorySize, GSMEM);
    cudaFuncSetAttribute(gemm_mma<true,false,false,false>, cudaFuncAttributeMaxDynamicSharedMemorySize, GSMEM);
    cudaFuncSetAttribute(gemm_mma<false,true,false,false>, cudaFuncAttributeMaxDynamicSharedMemorySize, GSMEM);
    cudaFuncSetAttribute(gemm_mma<true,false,false,true>,  cudaFuncAttributeMaxDynamicSharedMemorySize, GSMEM);

    split_hi<<<(ROWS * DIM) / 1024, 256>>>(x, x_h, (size_t)ROWS * DIM);
    transpose_split<<<dim3(QKVD / 32, DIM / 32, 1), 256>>>(W_qkv, Wqkvt_h, Wqkvt_l, QKVD, DIM, 0, 0);
    transpose_split<<<dim3(DIM / 32, DIM / 32, 1), 256>>>(W_proj, Wprojt_h, Wprojt_l, DIM, DIM, 0, 0);

    // 1) qkv = x @ W_qkv + b  (2-pass) -> split fp16 (hi + lo)
    gemm_mma<false,true,true,true><<<dim3(QKVD / 128, ROWS / 128, 1), 256, GSMEM>>>(
        x_h, DIM, 0, Wqkvt_h, Wqkvt_l, DIM, 0,
        nullptr, qkv_h, qkv_l, QKVD, 0, b_qkv, DIM, 1.0f);

    // 2) gw = softmax(q @ W_gp)
    gw_kernel2<<<ROWS / 64, 256>>>(qkv_h, qkv_l, W_gp, gw);

    // V^T per batch (both planes, one launch)
    transpose_half2<<<dim3(DIM / 32, SEQ / 32, BATCH), 256>>>(
        qkv_h + 2 * DIM, qkv_l + 2 * DIM, Vt_h, Vt_l,
        QKVD, SEQ, (long long)SEQ * QKVD, (long long)DIM * SEQ);

    // 3) S = scale * Q K^T  (2-pass: Qh*(Kh+Kl)) -> fp32
    gemm_mma<true,false,false,false><<<dim3(SEQ / 128, SEQ / 128, BATCH), 256, GSMEM>>>(
        qkv_h, QKVD, (long long)SEQ * QKVD,
        qkv_h + DIM, qkv_l + DIM, QKVD, (long long)SEQ * QKVD,
        S, nullptr, nullptr, SEQ, (long long)SEQ * SEQ, nullptr, DIM, scale);

    // 4) row stats (warp per row)
    rowstats_kernel2<<<ROWS / 8, 256>>>(S, rmax, rsum);

    // 5) modulate -> fp16 hi only
    modulate2<<<dim3(SEQ / 128, SEQ / 64, BATCH), 256>>>(S, gw, rmax, rsum, alpha, S_h);

    // 6) ov = W @ V  (2-pass: Wh*(Vh+Vl)) -> fp16 hi only
    gemm_mma<false,true,false,false><<<dim3(DIM / 128, SEQ / 128, BATCH), 256, GSMEM>>>(
        S_h, SEQ, (long long)SEQ * SEQ,
        Vt_h, Vt_l, SEQ, (long long)DIM * SEQ,
        nullptr, ov_h, nullptr, DIM, (long long)SEQ * DIM, nullptr, SEQ, 1.0f);

    // 7) out = ov @ W_proj + b  (2-pass: ovh*(Wh+Wl)) -> fp32
    gemm_mma<true,false,false,true><<<dim3(DIM / 128, ROWS / 128, 1), 256, GSMEM>>>(
        ov_h, DIM, 0, Wprojt_h, Wprojt_l, DIM, 0,
        out, nullptr, nullptr, DIM, 0, b_proj, DIM, 1.0f);
}

// round 13
// speedup vs baseline: 1.0493x; 1.0493x over previous
#include <cuda_runtime.h>
#include <cuda_fp16.h>
#include <math.h>
#include <stdint.h>

#define BATCH 16
#define SEQ   1024
#define DIM   768
#define GP    49
#define ROWS  (BATCH * SEQ)      // 16384
#define QKVD  (3 * DIM)          // 2304

// ---------------- scratch (device globals) ----------------------------------
__device__ float g_gw [(size_t)ROWS * GP];
__device__ float g_S  [(size_t)BATCH * SEQ * SEQ];
__device__ float g_rsum[ROWS];

__device__ half g_x_h   [(size_t)ROWS * DIM];
__device__ half g_qkv_h [(size_t)ROWS * QKVD];
__device__ half g_qkv_l [(size_t)ROWS * QKVD];
__device__ half g_S_h   [(size_t)BATCH * SEQ * SEQ];
__device__ half g_Vt_h  [(size_t)BATCH * DIM * SEQ];
__device__ half g_Vt_l  [(size_t)BATCH * DIM * SEQ];
__device__ half g_ov_h  [(size_t)ROWS * DIM];
__device__ half g_Wqkvt_h [(size_t)QKVD * DIM];
__device__ half g_Wqkvt_l [(size_t)QKVD * DIM];
__device__ half g_Wprojt_h[(size_t)DIM * DIM];
__device__ half g_Wprojt_l[(size_t)DIM * DIM];

// ============================ helpers =======================================
__device__ __forceinline__ uint32_t smem_u32(const void* p) {
    uint32_t a;
    asm("{ .reg .u64 t; cvta.to.shared.u64 t, %1; cvt.u32.u64 %0, t; }" : "=r"(a) : "l"(p));
    return a;
}
__device__ __forceinline__ void cp16(uint32_t s, const void* g) {
    asm volatile("cp.async.cg.shared.global [%0], [%1], 16;" :: "r"(s), "l"(g));
}
__device__ __forceinline__ void cp_commit() {
    asm volatile("cp.async.commit_group;" ::: "memory");
}
template<int N>
__device__ __forceinline__ void cp_wait() {
    asm volatile("cp.async.wait_group %0;" :: "n"(N) : "memory");
}
__device__ __forceinline__ void mma16816(float* d, const uint32_t* a, const uint32_t* b) {
    asm volatile(
        "mma.sync.aligned.m16n8k16.row.col.f32.f16.f16.f32 "
        "{%0,%1,%2,%3},{%4,%5,%6,%7},{%8,%9},{%0,%1,%2,%3};"
        : "+f"(d[0]), "+f"(d[1]), "+f"(d[2]), "+f"(d[3])
        : "r"(a[0]), "r"(a[1]), "r"(a[2]), "r"(a[3]), "r"(b[0]), "r"(b[1]));
}
__device__ __forceinline__ void ldmx4(uint32_t& r0, uint32_t& r1, uint32_t& r2, uint32_t& r3,
                                      uint32_t saddr) {
    asm volatile("ldmatrix.sync.aligned.m8n8.x4.shared.b16 {%0,%1,%2,%3}, [%4];"
                 : "=r"(r0), "=r"(r1), "=r"(r2), "=r"(r3) : "r"(saddr));
}
// swizzled byte offset within an 8KB plane (128 logical rows x 4 chunks of 16B)
__device__ __forceinline__ uint32_t swz(int row, int ch) {
    return (uint32_t)(((row >> 1) << 7) |
           (((((row & 1) << 2) + ch) ^ ((row >> 1) & 7)) << 4));
}

// ============== fp16-pair mma.sync GEMM: C = alpha*Ah*(Bh+Bl) (+bias) =======
// R11-proven pipeline: 128x128 tile, 256 thr, K-chunk 32, 4-stage ring,
// 3 planes/stage (A_h, B_h, B_l), prefetch depth 3, wait_group<=2.
// SUMEXP: fuse per-row sum(exp(C)) into the epilogue via atomicAdd (no-max
// softmax denominator; scores bounded so exp cannot overflow).
#define PLANE_B  8192u
#define STAGE_B  24576u
#define NSTAGE   4
#define GSMEM    (NSTAGE * STAGE_B)

template<bool WF32, bool WHI, bool WLO, bool BIAS, bool SUMEXP>
__global__ void __launch_bounds__(256, 2) gemm_mma(
    const half* __restrict__ Ah, int lda, long long strA,
    const half* __restrict__ Bh, const half* __restrict__ Bl, int ldb, long long strB,
    float* __restrict__ C, half* __restrict__ Ch, half* __restrict__ Cl,
    int ldc, long long strC, const float* __restrict__ bias,
    float* __restrict__ rsum, int K, float alpha)
{
    extern __shared__ __align__(16) char smraw[];
    const uint32_t sb = smem_u32(smraw);
    const int tid  = threadIdx.x;
    const int lane = tid & 31;
    const int w    = tid >> 5;
    const int wm   = w & 1;
    const int wn   = w >> 1;
    const int m0 = blockIdx.y * 128, n0 = blockIdx.x * 128;

    const half* Abh = Ah + (long long)blockIdx.z * strA + (long long)m0 * lda;
    const half* Bbh = Bh + (long long)blockIdx.z * strB + (long long)n0 * ldb;
    const half* Bbl = Bl + (long long)blockIdx.z * strB + (long long)n0 * ldb;

    float acc[4][4][4];
#pragma unroll
    for (int i = 0; i < 4; i++)
#pragma unroll
        for (int j = 0; j < 4; j++)
#pragma unroll
            for (int r = 0; r < 4; r++) acc[i][j][r] = 0.f;

    const int nch = K >> 5;

    auto issue = [&](int k0, int stg) {
        const uint32_t base = sb + (uint32_t)stg * STAGE_B;
#pragma unroll
        for (int i = 0; i < 6; i++) {
            const int plane = i >> 1;
            const int cid = ((i & 1) << 8) + tid;
            const int row = cid >> 2;
            const int ch  = cid & 3;
            const uint32_t so = base + (uint32_t)plane * PLANE_B + swz(row, ch);
            const half* gp;
            if      (plane == 0) gp = Abh + (long long)row * lda + k0 + ch * 8;
            else if (plane == 1) gp = Bbh + (long long)row * ldb + k0 + ch * 8;
            else                 gp = Bbl + (long long)row * ldb + k0 + ch * 8;
            cp16(so, gp);
        }
        cp_commit();
    };

    issue(0, 0);
    issue(32, 1);
    issue(64, 2);

    const int rowl = lane & 15;
    const int cb   = lane >> 4;

    for (int c = 0; c < nch; ++c) {
        const int st = c & (NSTAGE - 1);
        if      (c < nch - 2) cp_wait<2>();
        else if (c == nch - 2) cp_wait<1>();
        else                   cp_wait<0>();
        __syncthreads();
        if (c + 3 < nch) issue((c + 3) << 5, (c + 3) & (NSTAGE - 1));

        const uint32_t stA_h = sb + (uint32_t)st * STAGE_B;
        const uint32_t stB_h = stA_h + PLANE_B;
        const uint32_t stB_l = stA_h + 2 * PLANE_B;

#pragma unroll
        for (int ks = 0; ks < 2; ks++) {
            const int ch = 2 * ks + cb;
            uint32_t ah[4][4], bh[4][2], bl[4][2];
#pragma unroll
            for (int mi = 0; mi < 4; mi++) {
                int row = wm * 64 + mi * 16 + rowl;
                ldmx4(ah[mi][0], ah[mi][1], ah[mi][2], ah[mi][3], stA_h + swz(row, ch));
            }
#pragma unroll
            for (int p = 0; p < 2; p++) {
                int row = wn * 32 + p * 16 + rowl;
                ldmx4(bh[2*p][0], bh[2*p+1][0], bh[2*p][1], bh[2*p+1][1], stB_h + swz(row, ch));
            }
#pragma unroll
            for (int mi = 0; mi < 4; mi++)
#pragma unroll
                for (int ni = 0; ni < 4; ni++)
                    mma16816(acc[mi][ni], ah[mi], bh[ni]);
#pragma unroll
            for (int p = 0; p < 2; p++) {
                int row = wn * 32 + p * 16 + rowl;
                ldmx4(bl[2*p][0], bl[2*p+1][0], bl[2*p][1], bl[2*p+1][1], stB_l + swz(row, ch));
            }
#pragma unroll
            for (int mi = 0; mi < 4; mi++)
#pragma unroll
                for (int ni = 0; ni < 4; ni++)
                    mma16816(acc[mi][ni], ah[mi], bl[ni]);
        }
    }

    float* Cb  = WF32 ? C  + (long long)blockIdx.z * strC : nullptr;
    half*  Chb = WHI  ? Ch + (long long)blockIdx.z * strC : nullptr;
    half*  Clb = WLO  ? Cl + (long long)blockIdx.z * strC : nullptr;
    float* rs  = SUMEXP ? rsum + blockIdx.z * SEQ : nullptr;
    const int r0 = m0 + wm * 64 + (lane >> 2);
    const int c0 = n0 + wn * 32 + ((lane & 3) << 1);
#pragma unroll
    for (int mi = 0; mi < 4; mi++) {
        float es[2] = {0.f, 0.f};
#pragma unroll
        for (int ni = 0; ni < 4; ni++) {
            int cc = c0 + ni * 8;
            float bx = 0.f, by = 0.f;
            if (BIAS) { bx = bias[cc]; by = bias[cc + 1]; }
#pragma unroll
            for (int h = 0; h < 2; h++) {
                int rr = r0 + mi * 16 + h * 8;
                float vx = acc[mi][ni][h * 2 + 0] * alpha + bx;
                float vy = acc[mi][ni][h * 2 + 1] * alpha + by;
                long long off = (long long)rr * ldc + cc;
                if (WF32) *(float2*)(Cb + off) = make_float2(vx, vy);
                if (SUMEXP) es[h] += expf(vx) + expf(vy);
                if (WHI) {
                    half2 hh;
                    hh.x = __float2half_rn(vx); hh.y = __float2half_rn(vy);
                    *(half2*)(Chb + off) = hh;
                    if (WLO) {
                        half2 ll;
                        ll.x = __float2half_rn(vx - __half2float(hh.x));
                        ll.y = __float2half_rn(vy - __half2float(hh.y));
                        *(half2*)(Clb + off) = ll;
                    }
                }
            }
        }
        if (SUMEXP) {
#pragma unroll
            for (int h = 0; h < 2; h++) {
                float v = es[h];
                v += __shfl_xor_sync(0xffffffffu, v, 1);
                v += __shfl_xor_sync(0xffffffffu, v, 2);
                if ((lane & 3) == 0)
                    atomicAdd(rs + (r0 - m0) + m0 + mi * 16 + h * 8 - 0, v);
            }
        }
    }
}

// ================== fp32 -> fp16 hi-only ====================================
__global__ void __launch_bounds__(256) split_hi(
    const float* __restrict__ in, half* __restrict__ oh, size_t n)
{
    size_t i = ((size_t)blockIdx.x * 256 + threadIdx.x) * 4;
    if (i >= n) return;
    float4 v = *(const float4*)(in + i);
    half2 h0, h1;
    h0.x = __float2half_rn(v.x); h0.y = __float2half_rn(v.y);
    h1.x = __float2half_rn(v.z); h1.y = __float2half_rn(v.w);
    *(half2*)(oh + i) = h0; *(half2*)(oh + i + 2) = h1;
}

// ================== transpose + split fp32 -> fp16 pair =====================
__global__ void __launch_bounds__(256) transpose_split(
    const float* __restrict__ in, half* __restrict__ oh, half* __restrict__ ol,
    int ldin, int ldout, long long sIn, long long sOut)
{
    __shared__ float t[32][33];
    const float* ib = in + (long long)blockIdx.z * sIn;
    half* obh = oh + (long long)blockIdx.z * sOut;
    half* obl = ol + (long long)blockIdx.z * sOut;
    int r0 = blockIdx.y * 32, c0 = blockIdx.x * 32;
    int x = threadIdx.x & 31, y = threadIdx.x >> 5;
#pragma unroll
    for (int j = 0; j < 32; j += 8)
        t[y + j][x] = ib[(long long)(r0 + y + j) * ldin + c0 + x];
    __syncthreads();
#pragma unroll
    for (int j = 0; j < 32; j += 8) {
        float v = t[x][y + j];
        half h = __float2half_rn(v);
        half l = __float2half_rn(v - __half2float(h));
        long long o = (long long)(c0 + y + j) * ldout + r0 + x;
        obh[o] = h; obl[o] = l;
    }
}

// ======= transpose both half planes (V -> V^T), one launch ==================
__global__ void __launch_bounds__(256) transpose_half2(
    const half* __restrict__ inh, const half* __restrict__ inl,
    half* __restrict__ outh, half* __restrict__ outl,
    int ldin, int ldout, long long sIn, long long sOut)
{
    __shared__ half t[2][32][34];
    const half* ibh = inh + (long long)blockIdx.z * sIn;
    const half* ibl = inl + (long long)blockIdx.z * sIn;
    half* obh = outh + (long long)blockIdx.z * sOut;
    half* obl = outl + (long long)blockIdx.z * sOut;
    int r0 = blockIdx.y * 32, c0 = blockIdx.x * 32;
    int x = threadIdx.x & 31, y = threadIdx.x >> 5;
#pragma unroll
    for (int j = 0; j < 32; j += 8) {
        t[0][y + j][x] = ibh[(long long)(r0 + y + j) * ldin + c0 + x];
        t[1][y + j][x] = ibl[(long long)(r0 + y + j) * ldin + c0 + x];
    }
    __syncthreads();
#pragma unroll
    for (int j = 0; j < 32; j += 8) {
        long long o = (long long)(c0 + y + j) * ldout + r0 + x;
        obh[o] = t[0][x][y + j];
        obl[o] = t[1][x][y + j];
    }
}

// ---------------- gw = softmax(q @ W_gp), 64 rows / block --------------------
__global__ void __launch_bounds__(256) gw_kernel2(
    const half* __restrict__ qh, const half* __restrict__ ql,
    const float* __restrict__ Wgp, float* __restrict__ gw)
{
    __shared__ float wt[64][52];
    __shared__ float qt[64][65];
    __shared__ float lg[64][50];
    const int row0 = blockIdx.x * 64;
    const int tid = threadIdx.x;
    const int c  = tid & 63;
    const int rq = tid >> 6;

    float acc[16];
#pragma unroll
    for (int i = 0; i < 16; i++) acc[i] = 0.f;

    for (int kc = 0; kc < DIM / 64; kc++) {
        for (int idx = tid; idx < 64 * GP; idx += 256) {
            int kk = idx / GP, cc = idx - kk * GP;
            wt[kk][cc] = Wgp[(kc * 64 + kk) * GP + cc];
        }
        for (int idx = tid; idx < 4096; idx += 256) {
            int r = idx >> 6, kk = idx & 63;
            long long o = (long long)(row0 + r) * QKVD + kc * 64 + kk;
            qt[r][kk] = __half2float(qh[o]) + __half2float(ql[o]);
        }
        __syncthreads();
        if (c < GP) {
            for (int kk = 0; kk < 64; kk++) {
                float wv = wt[kk][c];
#pragma unroll
                for (int i = 0; i < 16; i++)
                    acc[i] = fmaf(qt[rq * 16 + i][kk], wv, acc[i]);
            }
        }
        __syncthreads();
    }
    if (c < GP)
#pragma unroll
        for (int i = 0; i < 16; i++) lg[rq * 16 + i][c] = acc[i];
    __syncthreads();
    if (tid < 64) {
        float m = lg[tid][0];
        for (int j = 1; j < GP; j++) m = fmaxf(m, lg[tid][j]);
        float s = 0.f;
        float e[GP];
        for (int j = 0; j < GP; j++) { e[j] = expf(lg[tid][j] - m); s += e[j]; }
        float inv = 1.f / s;
        for (int j = 0; j < GP; j++)
            gw[(long long)(row0 + tid) * GP + j] = e[j] * inv;
    }
}

// ------- W = exp(S)/rsum * (a + (1-a)*<gw_i,gw_m>) -> fp16 hi only -----------
__global__ void __launch_bounds__(256) modulate2(
    const float* __restrict__ S, const float* __restrict__ gw,
    const float* __restrict__ rsum,
    const float* __restrict__ alpha_p, half* __restrict__ Sh)
{
    __shared__ float gwm[128][51];
    const int b  = blockIdx.z;
    const int i0 = blockIdx.y * 64;
    const int m0 = blockIdx.x * 128;
    const int tid = threadIdx.x;

    for (int idx = tid; idx < 128 * GP; idx += 256) {
        int r = idx / GP, cc = idx - r * GP;
        gwm[r][cc] = gw[(long long)(b * SEQ + m0 + r) * GP + cc];
    }
    __syncthreads();

    const float a = 1.f / (1.f + expf(-alpha_p[0]));
    const float oma = 1.f - a;
    const int ml = tid & 63;
    const int rq = tid >> 6;

    for (int ri = 0; ri < 16; ri++) {
        const int il = ri * 4 + rq;
        const int grow = b * SEQ + i0 + il;
        const float* gp = gw + (long long)grow * GP;
        const float inv = 1.f / rsum[grow];
        const float* srow = S + (long long)grow * SEQ + m0;
        float d0 = 0.f, d1 = 0.f;
#pragma unroll
        for (int cc = 0; cc < GP; cc++) {
            float g = __ldg(gp + cc);
            d0 = fmaf(g, gwm[ml][cc], d0);
            d1 = fmaf(g, gwm[ml + 64][cc], d1);
        }
        float v0 = expf(srow[ml]) * inv * (a + oma * d0);
        float v1 = expf(srow[ml + 64]) * inv * (a + oma * d1);
        long long o = (long long)grow * SEQ + m0;
        Sh[o + ml]      = __float2half_rn(v0);
        Sh[o + ml + 64] = __float2half_rn(v1);
    }
}

// ---------------- launcher ---------------------------------------------------
extern "C" void kernel_launch(void* const* d_in, const int* in_sizes, int n_in,
                              void* d_out, int out_size)
{
    const float* x      = (const float*)d_in[0];
    const float* W_qkv  = (const float*)d_in[1];
    const float* b_qkv  = (const float*)d_in[2];
    const float* W_proj = (const float*)d_in[3];
    const float* b_proj = (const float*)d_in[4];
    const float* W_gp   = (const float*)d_in[5];
    const float* alpha  = (const float*)d_in[6];
    float* out = (float*)d_out;

    float *gw, *S, *rsum;
    half *x_h, *qkv_h, *qkv_l, *S_h, *Vt_h, *Vt_l, *ov_h;
    half *Wqkvt_h, *Wqkvt_l, *Wprojt_h, *Wprojt_l;
    cudaGetSymbolAddress((void**)&gw,   g_gw);
    cudaGetSymbolAddress((void**)&S,    g_S);
    cudaGetSymbolAddress((void**)&rsum, g_rsum);
    cudaGetSymbolAddress((void**)&x_h,  g_x_h);
    cudaGetSymbolAddress((void**)&qkv_h, g_qkv_h);
    cudaGetSymbolAddress((void**)&qkv_l, g_qkv_l);
    cudaGetSymbolAddress((void**)&S_h,  g_S_h);
    cudaGetSymbolAddress((void**)&Vt_h, g_Vt_h);
    cudaGetSymbolAddress((void**)&Vt_l, g_Vt_l);
    cudaGetSymbolAddress((void**)&ov_h, g_ov_h);
    cudaGetSymbolAddress((void**)&Wqkvt_h,  g_Wqkvt_h);
    cudaGetSymbolAddress((void**)&Wqkvt_l,  g_Wqkvt_l);
    cudaGetSymbolAddress((void**)&Wprojt_h, g_Wprojt_h);
    cudaGetSymbolAddress((void**)&Wprojt_l, g_Wprojt_l);

    const float scale = (float)(1.0 / sqrt((double)DIM));
    cudaFuncSetAttribute(gemm_mma<false,true,true,true,false>,  cudaFuncAttributeMaxDynamicSharedMemorySize, GSMEM);
    cudaFuncSetAttribute(gemm_mma<true,false,false,false,true>, cudaFuncAttributeMaxDynamicSharedMemorySize, GSMEM);
    cudaFuncSetAttribute(gemm_mma<false,true,false,false,false>,cudaFuncAttributeMaxDynamicSharedMemorySize, GSMEM);
    cudaFuncSetAttribute(gemm_mma<true,false,false,true,false>, cudaFuncAttributeMaxDynamicSharedMemorySize, GSMEM);

    split_hi<<<(ROWS * DIM) / 1024, 256>>>(x, x_h, (size_t)ROWS * DIM);
    transpose_split<<<dim3(QKVD / 32, DIM / 32, 1), 256>>>(W_qkv, Wqkvt_h, Wqkvt_l, QKVD, DIM, 0, 0);
    transpose_split<<<dim3(DIM / 32, DIM / 32, 1), 256>>>(W_proj, Wprojt_h, Wprojt_l, DIM, DIM, 0, 0);
    cudaMemsetAsync(rsum, 0, ROWS * sizeof(float));

    // 1) qkv = x @ W_qkv + b  (2-pass) -> split fp16 (hi + lo)
    gemm_mma<false,true,true,true,false><<<dim3(QKVD / 128, ROWS / 128, 1), 256, GSMEM>>>(
        x_h, DIM, 0, Wqkvt_h, Wqkvt_l, DIM, 0,
        nullptr, qkv_h, qkv_l, QKVD, 0, b_qkv, nullptr, DIM, 1.0f);

    // 2) gw = softmax(q @ W_gp)
    gw_kernel2<<<ROWS / 64, 256>>>(qkv_h, qkv_l, W_gp, gw);

    // V^T per batch (both planes, one launch)
    transpose_half2<<<dim3(DIM / 32, SEQ / 32, BATCH), 256>>>(
        qkv_h + 2 * DIM, qkv_l + 2 * DIM, Vt_h, Vt_l,
        QKVD, SEQ, (long long)SEQ * QKVD, (long long)DIM * SEQ);

    // 3) S = scale * Q K^T  -> fp32 + fused per-row sum(exp(S)) into rsum
    gemm_mma<true,false,false,false,true><<<dim3(SEQ / 128, SEQ / 128, BATCH), 256, GSMEM>>>(
        qkv_h, QKVD, (long long)SEQ * QKVD,
        qkv_h + DIM, qkv_l + DIM, QKVD, (long long)SEQ * QKVD,
        S, nullptr, nullptr, SEQ, (long long)SEQ * SEQ, nullptr, rsum, DIM, scale);

    // 4) modulate (no-max softmax: exp(s)/rsum) -> fp16 hi only
    modulate2<<<dim3(SEQ / 128, SEQ / 64, BATCH), 256>>>(S, gw, rsum, alpha, S_h);

    // 5) ov = W @ V  (2-pass) -> fp16 hi only
    gemm_mma<false,true,false,false,false><<<dim3(DIM / 128, SEQ / 128, BATCH), 256, GSMEM>>>(
        S_h, SEQ, (long long)SEQ * SEQ,
        Vt_h, Vt_l, SEQ, (long long)DIM * SEQ,
        nullptr, ov_h, nullptr, DIM, (long long)SEQ * DIM, nullptr, nullptr, SEQ, 1.0f);

    // 6) out = ov @ W_proj + b  (2-pass) -> fp32
    gemm_mma<true,false,false,true,false><<<dim3(DIM / 128, ROWS / 128, 1), 256, GSMEM>>>(
        ov_h, DIM, 0, Wprojt_h, Wprojt_l, DIM, 0,
        out, nullptr, nullptr, DIM, 0, b_proj, nullptr, DIM, 1.0f);
}

// round 15
// speedup vs baseline: 1.0696x; 1.0194x over previous
#include <cuda_runtime.h>
#include <cuda_fp16.h>
#include <math.h>
#include <stdint.h>

#define BATCH 16
#define SEQ   1024
#define DIM   768
#define GP    49
#define ROWS  (BATCH * SEQ)      // 16384
#define QKVD  (3 * DIM)          // 2304

// ---------------- scratch (device globals) ----------------------------------
__device__ float g_gw [(size_t)ROWS * GP];
__device__ float g_rsum[ROWS];

__device__ half g_x_h   [(size_t)ROWS * DIM];
__device__ half g_qkv_h [(size_t)ROWS * QKVD];
__device__ half g_qkv_l [(size_t)ROWS * QKVD];
__device__ half g_S_h   [(size_t)BATCH * SEQ * SEQ];   // exp(S) then weights
__device__ half g_Vt_h  [(size_t)BATCH * DIM * SEQ];
__device__ half g_Vt_l  [(size_t)BATCH * DIM * SEQ];
__device__ half g_ov_h  [(size_t)ROWS * DIM];
__device__ half g_Wqkvt_h [(size_t)QKVD * DIM];
__device__ half g_Wqkvt_l [(size_t)QKVD * DIM];
__device__ half g_Wprojt_h[(size_t)DIM * DIM];
__device__ half g_Wprojt_l[(size_t)DIM * DIM];

// ============================ helpers =======================================
__device__ __forceinline__ uint32_t smem_u32(const void* p) {
    uint32_t a;
    asm("{ .reg .u64 t; cvta.to.shared.u64 t, %1; cvt.u32.u64 %0, t; }" : "=r"(a) : "l"(p));
    return a;
}
__device__ __forceinline__ void cp16(uint32_t s, const void* g) {
    asm volatile("cp.async.cg.shared.global [%0], [%1], 16;" :: "r"(s), "l"(g));
}
__device__ __forceinline__ void cp_commit() {
    asm volatile("cp.async.commit_group;" ::: "memory");
}
template<int N>
__device__ __forceinline__ void cp_wait() {
    asm volatile("cp.async.wait_group %0;" :: "n"(N) : "memory");
}
__device__ __forceinline__ void mma16816(float* d, const uint32_t* a, const uint32_t* b) {
    asm volatile(
        "mma.sync.aligned.m16n8k16.row.col.f32.f16.f16.f32 "
        "{%0,%1,%2,%3},{%4,%5,%6,%7},{%8,%9},{%0,%1,%2,%3};"
        : "+f"(d[0]), "+f"(d[1]), "+f"(d[2]), "+f"(d[3])
        : "r"(a[0]), "r"(a[1]), "r"(a[2]), "r"(a[3]), "r"(b[0]), "r"(b[1]));
}
__device__ __forceinline__ void ldmx4(uint32_t& r0, uint32_t& r1, uint32_t& r2, uint32_t& r3,
                                      uint32_t saddr) {
    asm volatile("ldmatrix.sync.aligned.m8n8.x4.shared.b16 {%0,%1,%2,%3}, [%4];"
                 : "=r"(r0), "=r"(r1), "=r"(r2), "=r"(r3) : "r"(saddr));
}
// swizzled byte offset within an 8KB plane (128 logical rows x 4 chunks of 16B)
__device__ __forceinline__ uint32_t swz(int row, int ch) {
    return (uint32_t)(((row >> 1) << 7) |
           (((((row & 1) << 2) + ch) ^ ((row >> 1) & 7)) << 4));
}

// ============== fp16-pair mma.sync GEMM: C = alpha*Ah*(Bh+Bl) (+bias) =======
// R11-proven pipeline: 128x128 tile, 256 thr, K-chunk 32, 4-stage ring,
// 3 planes/stage (A_h, B_h, B_l), prefetch depth 3, wait_group<=2.
// EXPH: store fp16(exp(C)); SUMEXP: fused per-row sum(exp) into rsum.
#define PLANE_B  8192u
#define STAGE_B  24576u
#define NSTAGE   4
#define GSMEM    (NSTAGE * STAGE_B)

template<bool WF32, bool WHI, bool WLO, bool BIAS, bool SUMEXP, bool EXPH>
__global__ void __launch_bounds__(256, 2) gemm_mma(
    const half* __restrict__ Ah, int lda, long long strA,
    const half* __restrict__ Bh, const half* __restrict__ Bl, int ldb, long long strB,
    float* __restrict__ C, half* __restrict__ Ch, half* __restrict__ Cl,
    int ldc, long long strC, const float* __restrict__ bias,
    float* __restrict__ rsum, int K, float alpha)
{
    extern __shared__ __align__(16) char smraw[];
    const uint32_t sb = smem_u32(smraw);
    const int tid  = threadIdx.x;
    const int lane = tid & 31;
    const int w    = tid >> 5;
    const int wm   = w & 1;
    const int wn   = w >> 1;
    const int m0 = blockIdx.y * 128, n0 = blockIdx.x * 128;

    const half* Abh = Ah + (long long)blockIdx.z * strA + (long long)m0 * lda;
    const half* Bbh = Bh + (long long)blockIdx.z * strB + (long long)n0 * ldb;
    const half* Bbl = Bl + (long long)blockIdx.z * strB + (long long)n0 * ldb;

    float acc[4][4][4];
#pragma unroll
    for (int i = 0; i < 4; i++)
#pragma unroll
        for (int j = 0; j < 4; j++)
#pragma unroll
            for (int r = 0; r < 4; r++) acc[i][j][r] = 0.f;

    const int nch = K >> 5;

    auto issue = [&](int k0, int stg) {
        const uint32_t base = sb + (uint32_t)stg * STAGE_B;
#pragma unroll
        for (int i = 0; i < 6; i++) {
            const int plane = i >> 1;
            const int cid = ((i & 1) << 8) + tid;
            const int row = cid >> 2;
            const int ch  = cid & 3;
            const uint32_t so = base + (uint32_t)plane * PLANE_B + swz(row, ch);
            const half* gp;
            if      (plane == 0) gp = Abh + (long long)row * lda + k0 + ch * 8;
            else if (plane == 1) gp = Bbh + (long long)row * ldb + k0 + ch * 8;
            else                 gp = Bbl + (long long)row * ldb + k0 + ch * 8;
            cp16(so, gp);
        }
        cp_commit();
    };

    issue(0, 0);
    issue(32, 1);
    issue(64, 2);

    const int rowl = lane & 15;
    const int cb   = lane >> 4;

    for (int c = 0; c < nch; ++c) {
        const int st = c & (NSTAGE - 1);
        if      (c < nch - 2) cp_wait<2>();
        else if (c == nch - 2) cp_wait<1>();
        else                   cp_wait<0>();
        __syncthreads();
        if (c + 3 < nch) issue((c + 3) << 5, (c + 3) & (NSTAGE - 1));

        const uint32_t stA_h = sb + (uint32_t)st * STAGE_B;
        const uint32_t stB_h = stA_h + PLANE_B;
        const uint32_t stB_l = stA_h + 2 * PLANE_B;

#pragma unroll
        for (int ks = 0; ks < 2; ks++) {
            const int ch = 2 * ks + cb;
            uint32_t ah[4][4], bh[4][2], bl[4][2];
#pragma unroll
            for (int mi = 0; mi < 4; mi++) {
                int row = wm * 64 + mi * 16 + rowl;
                ldmx4(ah[mi][0], ah[mi][1], ah[mi][2], ah[mi][3], stA_h + swz(row, ch));
            }
#pragma unroll
            for (int p = 0; p < 2; p++) {
                int row = wn * 32 + p * 16 + rowl;
                ldmx4(bh[2*p][0], bh[2*p+1][0], bh[2*p][1], bh[2*p+1][1], stB_h + swz(row, ch));
            }
#pragma unroll
            for (int mi = 0; mi < 4; mi++)
#pragma unroll
                for (int ni = 0; ni < 4; ni++)
                    mma16816(acc[mi][ni], ah[mi], bh[ni]);
#pragma unroll
            for (int p = 0; p < 2; p++) {
                int row = wn * 32 + p * 16 + rowl;
                ldmx4(bl[2*p][0], bl[2*p+1][0], bl[2*p][1], bl[2*p+1][1], stB_l + swz(row, ch));
            }
#pragma unroll
            for (int mi = 0; mi < 4; mi++)
#pragma unroll
                for (int ni = 0; ni < 4; ni++)
                    mma16816(acc[mi][ni], ah[mi], bl[ni]);
        }
    }

    float* Cb  = WF32 ? C  + (long long)blockIdx.z * strC : nullptr;
    half*  Chb = WHI  ? Ch + (long long)blockIdx.z * strC : nullptr;
    half*  Clb = WLO  ? Cl + (long long)blockIdx.z * strC : nullptr;
    float* rs  = SUMEXP ? rsum + blockIdx.z * SEQ : nullptr;
    const int r0 = m0 + wm * 64 + (lane >> 2);
    const int c0 = n0 + wn * 32 + ((lane & 3) << 1);
#pragma unroll
    for (int mi = 0; mi < 4; mi++) {
        float es[2] = {0.f, 0.f};
#pragma unroll
        for (int ni = 0; ni < 4; ni++) {
            int cc = c0 + ni * 8;
            float bx = 0.f, by = 0.f;
            if (BIAS) { bx = bias[cc]; by = bias[cc + 1]; }
#pragma unroll
            for (int h = 0; h < 2; h++) {
                int rr = r0 + mi * 16 + h * 8;
                float vx = acc[mi][ni][h * 2 + 0] * alpha + bx;
                float vy = acc[mi][ni][h * 2 + 1] * alpha + by;
                long long off = (long long)rr * ldc + cc;
                if (EXPH) {
                    float ex = expf(vx), ey = expf(vy);
                    if (SUMEXP) es[h] += ex + ey;
                    half2 hh;
                    hh.x = __float2half_rn(ex); hh.y = __float2half_rn(ey);
                    *(half2*)(Chb + off) = hh;
                } else {
                    if (WF32) *(float2*)(Cb + off) = make_float2(vx, vy);
                    if (WHI) {
                        half2 hh;
                        hh.x = __float2half_rn(vx); hh.y = __float2half_rn(vy);
                        *(half2*)(Chb + off) = hh;
                        if (WLO) {
                            half2 ll;
                            ll.x = __float2half_rn(vx - __half2float(hh.x));
                            ll.y = __float2half_rn(vy - __half2float(hh.y));
                            *(half2*)(Clb + off) = ll;
                        }
                    }
                }
            }
        }
        if (SUMEXP) {
#pragma unroll
            for (int h = 0; h < 2; h++) {
                float v = es[h];
                v += __shfl_xor_sync(0xffffffffu, v, 1);
                v += __shfl_xor_sync(0xffffffffu, v, 2);
                if ((lane & 3) == 0)
                    atomicAdd(rs + r0 + mi * 16 + h * 8, v);
            }
        }
    }
}

// ================== fp32 -> fp16 hi-only ====================================
__global__ void __launch_bounds__(256) split_hi(
    const float* __restrict__ in, half* __restrict__ oh, size_t n)
{
    size_t i = ((size_t)blockIdx.x * 256 + threadIdx.x) * 4;
    if (i >= n) return;
    float4 v = *(const float4*)(in + i);
    half2 h0, h1;
    h0.x = __float2half_rn(v.x); h0.y = __float2half_rn(v.y);
    h1.x = __float2half_rn(v.z); h1.y = __float2half_rn(v.w);
    *(half2*)(oh + i) = h0; *(half2*)(oh + i + 2) = h1;
}

// ================== transpose + split fp32 -> fp16 pair =====================
__global__ void __launch_bounds__(256) transpose_split(
    const float* __restrict__ in, half* __restrict__ oh, half* __restrict__ ol,
    int ldin, int ldout, long long sIn, long long sOut)
{
    __shared__ float t[32][33];
    const float* ib = in + (long long)blockIdx.z * sIn;
    half* obh = oh + (long long)blockIdx.z * sOut;
    half* obl = ol + (long long)blockIdx.z * sOut;
    int r0 = blockIdx.y * 32, c0 = blockIdx.x * 32;
    int x = threadIdx.x & 31, y = threadIdx.x >> 5;
#pragma unroll
    for (int j = 0; j < 32; j += 8)
        t[y + j][x] = ib[(long long)(r0 + y + j) * ldin + c0 + x];
    __syncthreads();
#pragma unroll
    for (int j = 0; j < 32; j += 8) {
        float v = t[x][y + j];
        half h = __float2half_rn(v);
        half l = __float2half_rn(v - __half2float(h));
        long long o = (long long)(c0 + y + j) * ldout + r0 + x;
        obh[o] = h; obl[o] = l;
    }
}

// ======= transpose both half planes (V -> V^T), one launch ==================
__global__ void __launch_bounds__(256) transpose_half2(
    const half* __restrict__ inh, const half* __restrict__ inl,
    half* __restrict__ outh, half* __restrict__ outl,
    int ldin, int ldout, long long sIn, long long sOut)
{
    __shared__ half t[2][32][34];
    const half* ibh = inh + (long long)blockIdx.z * sIn;
    const half* ibl = inl + (long long)blockIdx.z * sIn;
    half* obh = outh + (long long)blockIdx.z * sOut;
    half* obl = outl + (long long)blockIdx.z * sOut;
    int r0 = blockIdx.y * 32, c0 = blockIdx.x * 32;
    int x = threadIdx.x & 31, y = threadIdx.x >> 5;
#pragma unroll
    for (int j = 0; j < 32; j += 8) {
        t[0][y + j][x] = ibh[(long long)(r0 + y + j) * ldin + c0 + x];
        t[1][y + j][x] = ibl[(long long)(r0 + y + j) * ldin + c0 + x];
    }
    __syncthreads();
#pragma unroll
    for (int j = 0; j < 32; j += 8) {
        long long o = (long long)(c0 + y + j) * ldout + r0 + x;
        obh[o] = t[0][x][y + j];
        obl[o] = t[1][x][y + j];
    }
}

// ------- gw = softmax(q @ W_gp), 64 rows / block, q-hi only ------------------
__global__ void __launch_bounds__(256) gw_kernel2(
    const half* __restrict__ qh,
    const float* __restrict__ Wgp, float* __restrict__ gw)
{
    __shared__ float wt[64][52];
    __shared__ float qt[64][65];
    __shared__ float lg[64][50];
    const int row0 = blockIdx.x * 64;
    const int tid = threadIdx.x;
    const int c  = tid & 63;
    const int rq = tid >> 6;

    float acc[16];
#pragma unroll
    for (int i = 0; i < 16; i++) acc[i] = 0.f;

    for (int kc = 0; kc < DIM / 64; kc++) {
        for (int idx = tid; idx < 64 * GP; idx += 256) {
            int kk = idx / GP, cc = idx - kk * GP;
            wt[kk][cc] = Wgp[(kc * 64 + kk) * GP + cc];
        }
        for (int idx = tid; idx < 4096; idx += 256) {
            int r = idx >> 6, kk = idx & 63;
            long long o = (long long)(row0 + r) * QKVD + kc * 64 + kk;
            qt[r][kk] = __half2float(qh[o]);
        }
        __syncthreads();
        if (c < GP) {
            for (int kk = 0; kk < 64; kk++) {
                float wv = wt[kk][c];
#pragma unroll
                for (int i = 0; i < 16; i++)
                    acc[i] = fmaf(qt[rq * 16 + i][kk], wv, acc[i]);
            }
        }
        __syncthreads();
    }
    if (c < GP)
#pragma unroll
        for (int i = 0; i < 16; i++) lg[rq * 16 + i][c] = acc[i];
    __syncthreads();
    if (tid < 64) {
        float m = lg[tid][0];
        for (int j = 1; j < GP; j++) m = fmaxf(m, lg[tid][j]);
        float s = 0.f;
        float e[GP];
        for (int j = 0; j < GP; j++) { e[j] = expf(lg[tid][j] - m); s += e[j]; }
        float inv = 1.f / s;
        for (int j = 0; j < GP; j++)
            gw[(long long)(row0 + tid) * GP + j] = e[j] * inv;
    }
}

// --- W = e/rsum * (a + (1-a)*<gw_i,gw_m>), in place on fp16 exp buffer -------
// 64 rows x 128 cols per block; thread handles one half2 (2 adjacent cols).
__global__ void __launch_bounds__(256) modulate2(
    half* __restrict__ Sh, const float* __restrict__ gw,
    const float* __restrict__ rsum, const float* __restrict__ alpha_p)
{
    __shared__ float gwm[128][51];
    const int b  = blockIdx.z;
    const int i0 = blockIdx.y * 64;
    const int m0 = blockIdx.x * 128;
    const int tid = threadIdx.x;

    for (int idx = tid; idx < 128 * GP; idx += 256) {
        int r = idx / GP, cc = idx - r * GP;
        gwm[r][cc] = gw[(long long)(b * SEQ + m0 + r) * GP + cc];
    }
    __syncthreads();

    const float a = 1.f / (1.f + expf(-alpha_p[0]));
    const float oma = 1.f - a;
    const int cw = tid & 63;      // half2 column index: cols 2*cw, 2*cw+1
    const int rq = tid >> 6;      // 4 row lanes

    for (int ri = 0; ri < 16; ri++) {
        const int il = ri * 4 + rq;
        const int grow = b * SEQ + i0 + il;
        const float* gp = gw + (long long)grow * GP;
        const float inv = 1.f / rsum[grow];
        half2* srow = (half2*)(Sh + (long long)grow * SEQ + m0);
        float d0 = 0.f, d1 = 0.f;
#pragma unroll
        for (int cc = 0; cc < GP; cc++) {
            float g = __ldg(gp + cc);
            d0 = fmaf(g, gwm[2 * cw][cc], d0);
            d1 = fmaf(g, gwm[2 * cw + 1][cc], d1);
        }
        half2 e = srow[cw];
        float v0 = __half2float(e.x) * inv * (a + oma * d0);
        float v1 = __half2float(e.y) * inv * (a + oma * d1);
        half2 o; o.x = __float2half_rn(v0); o.y = __float2half_rn(v1);
        srow[cw] = o;
    }
}

// ---------------- launcher ---------------------------------------------------
extern "C" void kernel_launch(void* const* d_in, const int* in_sizes, int n_in,
                              void* d_out, int out_size)
{
    const float* x      = (const float*)d_in[0];
    const float* W_qkv  = (const float*)d_in[1];
    const float* b_qkv  = (const float*)d_in[2];
    const float* W_proj = (const float*)d_in[3];
    const float* b_proj = (const float*)d_in[4];
    const float* W_gp   = (const float*)d_in[5];
    const float* alpha  = (const float*)d_in[6];
    float* out = (float*)d_out;

    float *gw, *rsum;
    half *x_h, *qkv_h, *qkv_l, *S_h, *Vt_h, *Vt_l, *ov_h;
    half *Wqkvt_h, *Wqkvt_l, *Wprojt_h, *Wprojt_l;
    cudaGetSymbolAddress((void**)&gw,   g_gw);
    cudaGetSymbolAddress((void**)&rsum, g_rsum);
    cudaGetSymbolAddress((void**)&x_h,  g_x_h);
    cudaGetSymbolAddress((void**)&qkv_h, g_qkv_h);
    cudaGetSymbolAddress((void**)&qkv_l, g_qkv_l);
    cudaGetSymbolAddress((void**)&S_h,  g_S_h);
    cudaGetSymbolAddress((void**)&Vt_h, g_Vt_h);
    cudaGetSymbolAddress((void**)&Vt_l, g_Vt_l);
    cudaGetSymbolAddress((void**)&ov_h, g_ov_h);
    cudaGetSymbolAddress((void**)&Wqkvt_h,  g_Wqkvt_h);
    cudaGetSymbolAddress((void**)&Wqkvt_l,  g_Wqkvt_l);
    cudaGetSymbolAddress((void**)&Wprojt_h, g_Wprojt_h);
    cudaGetSymbolAddress((void**)&Wprojt_l, g_Wprojt_l);

    const float scale = (float)(1.0 / sqrt((double)DIM));
    cudaFuncSetAttribute(gemm_mma<false,true,true,true,false,false>,  cudaFuncAttributeMaxDynamicSharedMemorySize, GSMEM);
    cudaFuncSetAttribute(gemm_mma<false,true,false,false,true,true>,  cudaFuncAttributeMaxDynamicSharedMemorySize, GSMEM);
    cudaFuncSetAttribute(gemm_mma<false,true,false,false,false,false>,cudaFuncAttributeMaxDynamicSharedMemorySize, GSMEM);
    cudaFuncSetAttribute(gemm_mma<true,false,false,true,false,false>, cudaFuncAttributeMaxDynamicSharedMemorySize, GSMEM);

    split_hi<<<(ROWS * DIM) / 1024, 256>>>(x, x_h, (size_t)ROWS * DIM);
    transpose_split<<<dim3(QKVD / 32, DIM / 32, 1), 256>>>(W_qkv, Wqkvt_h, Wqkvt_l, QKVD, DIM, 0, 0);
    transpose_split<<<dim3(DIM / 32, DIM / 32, 1), 256>>>(W_proj, Wprojt_h, Wprojt_l, DIM, DIM, 0, 0);
    cudaMemsetAsync(rsum, 0, ROWS * sizeof(float));

    // 1) qkv = x @ W_qkv + b  (2-pass) -> split fp16 (hi + lo)
    gemm_mma<false,true,true,true,false,false><<<dim3(QKVD / 128, ROWS / 128, 1), 256, GSMEM>>>(
        x_h, DIM, 0, Wqkvt_h, Wqkvt_l, DIM, 0,
        nullptr, qkv_h, qkv_l, QKVD, 0, b_qkv, nullptr, DIM, 1.0f);

    // 2) gw = softmax(q @ W_gp)  (q-hi only)
    gw_kernel2<<<ROWS / 64, 256>>>(qkv_h, W_gp, gw);

    // V^T per batch (both planes, one launch)
    transpose_half2<<<dim3(DIM / 32, SEQ / 32, BATCH), 256>>>(
        qkv_h + 2 * DIM, qkv_l + 2 * DIM, Vt_h, Vt_l,
        QKVD, SEQ, (long long)SEQ * QKVD, (long long)DIM * SEQ);

    // 3) S-GEMM -> exp(scale*QK^T) stored fp16 + fused row sums (fp32 exact)
    gemm_mma<false,true,false,false,true,true><<<dim3(SEQ / 128, SEQ / 128, BATCH), 256, GSMEM>>>(
        qkv_h, QKVD, (long long)SEQ * QKVD,
        qkv_h + DIM, qkv_l + DIM, QKVD, (long long)SEQ * QKVD,
        nullptr, S_h, nullptr, SEQ, (long long)SEQ * SEQ, nullptr, rsum, DIM, scale);

    // 4) modulate in place: S_h <- S_h/rsum * (a + (1-a)*group)
    modulate2<<<dim3(SEQ / 128, SEQ / 64, BATCH), 256>>>(S_h, gw, rsum, alpha);

    // 5) ov = W @ V  (2-pass) -> fp16 hi only
    gemm_mma<false,true,false,false,false,false><<<dim3(DIM / 128, SEQ / 128, BATCH), 256, GSMEM>>>(
        S_h, SEQ, (long long)SEQ * SEQ,
        Vt_h, Vt_l, SEQ, (long long)DIM * SEQ,
        nullptr, ov_h, nullptr, DIM, (long long)SEQ * DIM, nullptr, nullptr, SEQ, 1.0f);

    // 6) out = ov @ W_proj + b  (2-pass) -> fp32
    gemm_mma<true,false,false,true,false,false><<<dim3(DIM / 128, ROWS / 128, 1), 256, GSMEM>>>(
        ov_h, DIM, 0, Wprojt_h, Wprojt_l, DIM, 0,
        out, nullptr, nullptr, DIM, 0, b_proj, nullptr, DIM, 1.0f);
}

// round 16
// speedup vs baseline: 1.2442x; 1.1633x over previous
#include <cuda_runtime.h>
#include <cuda_fp16.h>
#include <math.h>
#include <stdint.h>

#define BATCH 16
#define SEQ   1024
#define DIM   768
#define GP    49
#define ROWS  (BATCH * SEQ)      // 16384
#define QKVD  (3 * DIM)          // 2304

// ---------------- scratch (device globals) ----------------------------------
__device__ float g_gw [(size_t)ROWS * GP];
__device__ float g_rsum[ROWS];

__device__ half g_x_h   [(size_t)ROWS * DIM];
__device__ half g_qkv_h [(size_t)ROWS * QKVD];
__device__ half g_qkv_l [(size_t)ROWS * QKVD];   // only K-slice [DIM,2DIM) written/read
__device__ half g_S_h   [(size_t)BATCH * SEQ * SEQ];
__device__ half g_Vt_h  [(size_t)BATCH * DIM * SEQ];
__device__ half g_ov_h  [(size_t)ROWS * DIM];
__device__ half g_Wqkvt_h [(size_t)QKVD * DIM];
__device__ half g_Wqkvt_l [(size_t)QKVD * DIM];
__device__ half g_Wprojt_h[(size_t)DIM * DIM];

// ============================ helpers =======================================
__device__ __forceinline__ uint32_t smem_u32(const void* p) {
    uint32_t a;
    asm("{ .reg .u64 t; cvta.to.shared.u64 t, %1; cvt.u32.u64 %0, t; }" : "=r"(a) : "l"(p));
    return a;
}
__device__ __forceinline__ void cp16(uint32_t s, const void* g) {
    asm volatile("cp.async.cg.shared.global [%0], [%1], 16;" :: "r"(s), "l"(g));
}
__device__ __forceinline__ void cp_commit() {
    asm volatile("cp.async.commit_group;" ::: "memory");
}
template<int N>
__device__ __forceinline__ void cp_wait() {
    asm volatile("cp.async.wait_group %0;" :: "n"(N) : "memory");
}
__device__ __forceinline__ void mma16816(float* d, const uint32_t* a, const uint32_t* b) {
    asm volatile(
        "mma.sync.aligned.m16n8k16.row.col.f32.f16.f16.f32 "
        "{%0,%1,%2,%3},{%4,%5,%6,%7},{%8,%9},{%0,%1,%2,%3};"
        : "+f"(d[0]), "+f"(d[1]), "+f"(d[2]), "+f"(d[3])
        : "r"(a[0]), "r"(a[1]), "r"(a[2]), "r"(a[3]), "r"(b[0]), "r"(b[1]));
}
__device__ __forceinline__ void ldmx4(uint32_t& r0, uint32_t& r1, uint32_t& r2, uint32_t& r3,
                                      uint32_t saddr) {
    asm volatile("ldmatrix.sync.aligned.m8n8.x4.shared.b16 {%0,%1,%2,%3}, [%4];"
                 : "=r"(r0), "=r"(r1), "=r"(r2), "=r"(r3) : "r"(saddr));
}
// swizzled byte offset within an 8KB plane (128 logical rows x 4 chunks of 16B)
__device__ __forceinline__ uint32_t swz(int row, int ch) {
    return (uint32_t)(((row >> 1) << 7) |
           (((((row & 1) << 2) + ch) ^ ((row >> 1) & 7)) << 4));
}

// ============ fp16-pair mma.sync GEMM: C = alpha*Ah*(Bh[+Bl]) (+bias) =======
// NPASS=2: Ah*(Bh+Bl); NPASS=1: Ah*Bh (pure fp16 inputs).
// R11 pipeline: 128x128 tile, 256 thr, K-chunk 32, 4-stage ring, depth 3.
// EXPH: store fp16(exp(C)); SUMEXP: fused per-row sum(exp) into rsum.
// WLO writes gated to n-blocks [lo_n0, lo_n1).
#define PLANE_B  8192u
#define STAGE_B  24576u
#define NSTAGE   4
#define GSMEM    (NSTAGE * STAGE_B)

template<int NPASS, bool WF32, bool WHI, bool WLO, bool BIAS, bool SUMEXP, bool EXPH>
__global__ void __launch_bounds__(256, 2) gemm_mma(
    const half* __restrict__ Ah, int lda, long long strA,
    const half* __restrict__ Bh, const half* __restrict__ Bl, int ldb, long long strB,
    float* __restrict__ C, half* __restrict__ Ch, half* __restrict__ Cl,
    int ldc, long long strC, const float* __restrict__ bias,
    float* __restrict__ rsum, int K, float alpha, int lo_n0, int lo_n1)
{
    extern __shared__ __align__(16) char smraw[];
    const uint32_t sb = smem_u32(smraw);
    const int tid  = threadIdx.x;
    const int lane = tid & 31;
    const int w    = tid >> 5;
    const int wm   = w & 1;
    const int wn   = w >> 1;
    const int m0 = blockIdx.y * 128, n0 = blockIdx.x * 128;

    const half* Abh = Ah + (long long)blockIdx.z * strA + (long long)m0 * lda;
    const half* Bbh = Bh + (long long)blockIdx.z * strB + (long long)n0 * ldb;
    const half* Bbl = (NPASS == 2) ? Bl + (long long)blockIdx.z * strB + (long long)n0 * ldb : nullptr;

    float acc[4][4][4];
#pragma unroll
    for (int i = 0; i < 4; i++)
#pragma unroll
        for (int j = 0; j < 4; j++)
#pragma unroll
            for (int r = 0; r < 4; r++) acc[i][j][r] = 0.f;

    const int nch = K >> 5;
    const int NCP = (NPASS == 2) ? 6 : 4;

    auto issue = [&](int k0, int stg) {
        const uint32_t base = sb + (uint32_t)stg * STAGE_B;
#pragma unroll
        for (int i = 0; i < NCP; i++) {
            const int plane = i >> 1;
            const int cid = ((i & 1) << 8) + tid;
            const int row = cid >> 2;
            const int ch  = cid & 3;
            const uint32_t so = base + (uint32_t)plane * PLANE_B + swz(row, ch);
            const half* gp;
            if      (plane == 0) gp = Abh + (long long)row * lda + k0 + ch * 8;
            else if (plane == 1) gp = Bbh + (long long)row * ldb + k0 + ch * 8;
            else                 gp = Bbl + (long long)row * ldb + k0 + ch * 8;
            cp16(so, gp);
        }
        cp_commit();
    };

    issue(0, 0);
    issue(32, 1);
    issue(64, 2);

    const int rowl = lane & 15;
    const int cb   = lane >> 4;

    for (int c = 0; c < nch; ++c) {
        const int st = c & (NSTAGE - 1);
        if      (c < nch - 2) cp_wait<2>();
        else if (c == nch - 2) cp_wait<1>();
        else                   cp_wait<0>();
        __syncthreads();
        if (c + 3 < nch) issue((c + 3) << 5, (c + 3) & (NSTAGE - 1));

        const uint32_t stA_h = sb + (uint32_t)st * STAGE_B;
        const uint32_t stB_h = stA_h + PLANE_B;
        const uint32_t stB_l = stA_h + 2 * PLANE_B;

#pragma unroll
        for (int ks = 0; ks < 2; ks++) {
            const int ch = 2 * ks + cb;
            uint32_t ah[4][4], bh[4][2];
#pragma unroll
            for (int mi = 0; mi < 4; mi++) {
                int row = wm * 64 + mi * 16 + rowl;
                ldmx4(ah[mi][0], ah[mi][1], ah[mi][2], ah[mi][3], stA_h + swz(row, ch));
            }
#pragma unroll
            for (int p = 0; p < 2; p++) {
                int row = wn * 32 + p * 16 + rowl;
                ldmx4(bh[2*p][0], bh[2*p+1][0], bh[2*p][1], bh[2*p+1][1], stB_h + swz(row, ch));
            }
#pragma unroll
            for (int mi = 0; mi < 4; mi++)
#pragma unroll
                for (int ni = 0; ni < 4; ni++)
                    mma16816(acc[mi][ni], ah[mi], bh[ni]);
            if (NPASS == 2) {
                uint32_t bl[4][2];
#pragma unroll
                for (int p = 0; p < 2; p++) {
                    int row = wn * 32 + p * 16 + rowl;
                    ldmx4(bl[2*p][0], bl[2*p+1][0], bl[2*p][1], bl[2*p+1][1], stB_l + swz(row, ch));
                }
#pragma unroll
                for (int mi = 0; mi < 4; mi++)
#pragma unroll
                    for (int ni = 0; ni < 4; ni++)
                        mma16816(acc[mi][ni], ah[mi], bl[ni]);
            }
        }
    }

    float* Cb  = WF32 ? C  + (long long)blockIdx.z * strC : nullptr;
    half*  Chb = WHI  ? Ch + (long long)blockIdx.z * strC : nullptr;
    half*  Clb = WLO  ? Cl + (long long)blockIdx.z * strC : nullptr;
    const bool wlo = WLO && ((int)blockIdx.x >= lo_n0) && ((int)blockIdx.x < lo_n1);
    float* rs  = SUMEXP ? rsum + blockIdx.z * SEQ : nullptr;
    const int r0 = m0 + wm * 64 + (lane >> 2);
    const int c0 = n0 + wn * 32 + ((lane & 3) << 1);
#pragma unroll
    for (int mi = 0; mi < 4; mi++) {
        float es[2] = {0.f, 0.f};
#pragma unroll
        for (int ni = 0; ni < 4; ni++) {
            int cc = c0 + ni * 8;
            float bx = 0.f, by = 0.f;
            if (BIAS) { bx = bias[cc]; by = bias[cc + 1]; }
#pragma unroll
            for (int h = 0; h < 2; h++) {
                int rr = r0 + mi * 16 + h * 8;
                float vx = acc[mi][ni][h * 2 + 0] * alpha + bx;
                float vy = acc[mi][ni][h * 2 + 1] * alpha + by;
                long long off = (long long)rr * ldc + cc;
                if (EXPH) {
                    float ex = expf(vx), ey = expf(vy);
                    if (SUMEXP) es[h] += ex + ey;
                    half2 hh;
                    hh.x = __float2half_rn(ex); hh.y = __float2half_rn(ey);
                    *(half2*)(Chb + off) = hh;
                } else {
                    if (WF32) *(float2*)(Cb + off) = make_float2(vx, vy);
                    if (WHI) {
                        half2 hh;
                        hh.x = __float2half_rn(vx); hh.y = __float2half_rn(vy);
                        *(half2*)(Chb + off) = hh;
                        if (WLO && wlo) {
                            half2 ll;
                            ll.x = __float2half_rn(vx - __half2float(hh.x));
                            ll.y = __float2half_rn(vy - __half2float(hh.y));
                            *(half2*)(Clb + off) = ll;
                        }
                    }
                }
            }
        }
        if (SUMEXP) {
#pragma unroll
            for (int h = 0; h < 2; h++) {
                float v = es[h];
                v += __shfl_xor_sync(0xffffffffu, v, 1);
                v += __shfl_xor_sync(0xffffffffu, v, 2);
                if ((lane & 3) == 0)
                    atomicAdd(rs + r0 + mi * 16 + h * 8, v);
            }
        }
    }
}

// ================== fp32 -> fp16 hi-only ====================================
__global__ void __launch_bounds__(256) split_hi(
    const float* __restrict__ in, half* __restrict__ oh, size_t n)
{
    size_t i = ((size_t)blockIdx.x * 256 + threadIdx.x) * 4;
    if (i >= n) return;
    float4 v = *(const float4*)(in + i);
    half2 h0, h1;
    h0.x = __float2half_rn(v.x); h0.y = __float2half_rn(v.y);
    h1.x = __float2half_rn(v.z); h1.y = __float2half_rn(v.w);
    *(half2*)(oh + i) = h0; *(half2*)(oh + i + 2) = h1;
}

// ================== transpose + split fp32 -> fp16 pair =====================
__global__ void __launch_bounds__(256) transpose_split(
    const float* __restrict__ in, half* __restrict__ oh, half* __restrict__ ol,
    int ldin, int ldout, long long sIn, long long sOut)
{
    __shared__ float t[32][33];
    const float* ib = in + (long long)blockIdx.z * sIn;
    half* obh = oh + (long long)blockIdx.z * sOut;
    half* obl = ol + (long long)blockIdx.z * sOut;
    int r0 = blockIdx.y * 32, c0 = blockIdx.x * 32;
    int x = threadIdx.x & 31, y = threadIdx.x >> 5;
#pragma unroll
    for (int j = 0; j < 32; j += 8)
        t[y + j][x] = ib[(long long)(r0 + y + j) * ldin + c0 + x];
    __syncthreads();
#pragma unroll
    for (int j = 0; j < 32; j += 8) {
        float v = t[x][y + j];
        half h = __float2half_rn(v);
        long long o = (long long)(c0 + y + j) * ldout + r0 + x;
        obh[o] = h;
        if (ol) ol[o] = __float2half_rn(v - __half2float(h));
    }
}

// ======== transpose single half plane (V_h -> V^T_h) ========================
__global__ void __launch_bounds__(256) transpose_half(
    const half* __restrict__ in, half* __restrict__ out,
    int ldin, int ldout, long long sIn, long long sOut)
{
    __shared__ half t[32][34];
    const half* ib = in + (long long)blockIdx.z * sIn;
    half* ob = out + (long long)blockIdx.z * sOut;
    int r0 = blockIdx.y * 32, c0 = blockIdx.x * 32;
    int x = threadIdx.x & 31, y = threadIdx.x >> 5;
#pragma unroll
    for (int j = 0; j < 32; j += 8)
        t[y + j][x] = ib[(long long)(r0 + y + j) * ldin + c0 + x];
    __syncthreads();
#pragma unroll
    for (int j = 0; j < 32; j += 8)
        ob[(long long)(c0 + y + j) * ldout + r0 + x] = t[x][y + j];
}

// ------- gw = softmax(q @ W_gp), 64 rows / block, q-hi only ------------------
__global__ void __launch_bounds__(256) gw_kernel2(
    const half* __restrict__ qh,
    const float* __restrict__ Wgp, float* __restrict__ gw)
{
    __shared__ float wt[64][52];
    __shared__ float qt[64][65];
    __shared__ float lg[64][50];
    const int row0 = blockIdx.x * 64;
    const int tid = threadIdx.x;
    const int c  = tid & 63;
    const int rq = tid >> 6;

    float acc[16];
#pragma unroll
    for (int i = 0; i < 16; i++) acc[i] = 0.f;

    for (int kc = 0; kc < DIM / 64; kc++) {
        for (int idx = tid; idx < 64 * GP; idx += 256) {
            int kk = idx / GP, cc = idx - kk * GP;
            wt[kk][cc] = Wgp[(kc * 64 + kk) * GP + cc];
        }
        for (int idx = tid; idx < 4096; idx += 256) {
            int r = idx >> 6, kk = idx & 63;
            long long o = (long long)(row0 + r) * QKVD + kc * 64 + kk;
            qt[r][kk] = __half2float(qh[o]);
        }
        __syncthreads();
        if (c < GP) {
            for (int kk = 0; kk < 64; kk++) {
                float wv = wt[kk][c];
#pragma unroll
                for (int i = 0; i < 16; i++)
                    acc[i] = fmaf(qt[rq * 16 + i][kk], wv, acc[i]);
            }
        }
        __syncthreads();
    }
    if (c < GP)
#pragma unroll
        for (int i = 0; i < 16; i++) lg[rq * 16 + i][c] = acc[i];
    __syncthreads();
    if (tid < 64) {
        float m = lg[tid][0];
        for (int j = 1; j < GP; j++) m = fmaxf(m, lg[tid][j]);
        float s = 0.f;
        float e[GP];
        for (int j = 0; j < GP; j++) { e[j] = expf(lg[tid][j] - m); s += e[j]; }
        float inv = 1.f / s;
        for (int j = 0; j < GP; j++)
            gw[(long long)(row0 + tid) * GP + j] = e[j] * inv;
    }
}

// --- W = e/rsum * (a + (1-a)*<gw_i,gw_m>), in place on fp16 exp buffer -------
__global__ void __launch_bounds__(256) modulate2(
    half* __restrict__ Sh, const float* __restrict__ gw,
    const float* __restrict__ rsum, const float* __restrict__ alpha_p)
{
    __shared__ float gwm[128][51];
    const int b  = blockIdx.z;
    const int i0 = blockIdx.y * 64;
    const int m0 = blockIdx.x * 128;
    const int tid = threadIdx.x;

    for (int idx = tid; idx < 128 * GP; idx += 256) {
        int r = idx / GP, cc = idx - r * GP;
        gwm[r][cc] = gw[(long long)(b * SEQ + m0 + r) * GP + cc];
    }
    __syncthreads();

    const float a = 1.f / (1.f + expf(-alpha_p[0]));
    const float oma = 1.f - a;
    const int cw = tid & 63;      // half2 column index
    const int rq = tid >> 6;      // 4 row lanes

    for (int ri = 0; ri < 16; ri++) {
        const int il = ri * 4 + rq;
        const int grow = b * SEQ + i0 + il;
        const float* gp = gw + (long long)grow * GP;
        const float inv = 1.f / rsum[grow];
        half2* srow = (half2*)(Sh + (long long)grow * SEQ + m0);
        float d0 = 0.f, d1 = 0.f;
#pragma unroll
        for (int cc = 0; cc < GP; cc++) {
            float g = __ldg(gp + cc);
            d0 = fmaf(g, gwm[2 * cw][cc], d0);
            d1 = fmaf(g, gwm[2 * cw + 1][cc], d1);
        }
        half2 e = srow[cw];
        float v0 = __half2float(e.x) * inv * (a + oma * d0);
        float v1 = __half2float(e.y) * inv * (a + oma * d1);
        half2 o; o.x = __float2half_rn(v0); o.y = __float2half_rn(v1);
        srow[cw] = o;
    }
}

// ---------------- launcher ---------------------------------------------------
extern "C" void kernel_launch(void* const* d_in, const int* in_sizes, int n_in,
                              void* d_out, int out_size)
{
    const float* x      = (const float*)d_in[0];
    const float* W_qkv  = (const float*)d_in[1];
    const float* b_qkv  = (const float*)d_in[2];
    const float* W_proj = (const float*)d_in[3];
    const float* b_proj = (const float*)d_in[4];
    const float* W_gp   = (const float*)d_in[5];
    const float* alpha  = (const float*)d_in[6];
    float* out = (float*)d_out;

    float *gw, *rsum;
    half *x_h, *qkv_h, *qkv_l, *S_h, *Vt_h, *ov_h;
    half *Wqkvt_h, *Wqkvt_l, *Wprojt_h;
    cudaGetSymbolAddress((void**)&gw,   g_gw);
    cudaGetSymbolAddress((void**)&rsum, g_rsum);
    cudaGetSymbolAddress((void**)&x_h,  g_x_h);
    cudaGetSymbolAddress((void**)&qkv_h, g_qkv_h);
    cudaGetSymbolAddress((void**)&qkv_l, g_qkv_l);
    cudaGetSymbolAddress((void**)&S_h,  g_S_h);
    cudaGetSymbolAddress((void**)&Vt_h, g_Vt_h);
    cudaGetSymbolAddress((void**)&ov_h, g_ov_h);
    cudaGetSymbolAddress((void**)&Wqkvt_h,  g_Wqkvt_h);
    cudaGetSymbolAddress((void**)&Wqkvt_l,  g_Wqkvt_l);
    cudaGetSymbolAddress((void**)&Wprojt_h, g_Wprojt_h);

    const float scale = (float)(1.0 / sqrt((double)DIM));
    cudaFuncSetAttribute(gemm_mma<2,false,true,true,true,false,false>,  cudaFuncAttributeMaxDynamicSharedMemorySize, GSMEM);
    cudaFuncSetAttribute(gemm_mma<2,false,true,false,false,true,true>,  cudaFuncAttributeMaxDynamicSharedMemorySize, GSMEM);
    cudaFuncSetAttribute(gemm_mma<1,false,true,false,false,false,false>,cudaFuncAttributeMaxDynamicSharedMemorySize, GSMEM);
    cudaFuncSetAttribute(gemm_mma<1,true,false,false,true,false,false>, cudaFuncAttributeMaxDynamicSharedMemorySize, GSMEM);

    split_hi<<<(ROWS * DIM) / 1024, 256>>>(x, x_h, (size_t)ROWS * DIM);
    transpose_split<<<dim3(QKVD / 32, DIM / 32, 1), 256>>>(W_qkv, Wqkvt_h, Wqkvt_l, QKVD, DIM, 0, 0);
    transpose_split<<<dim3(DIM / 32, DIM / 32, 1), 256>>>(W_proj, Wprojt_h, nullptr, DIM, DIM, 0, 0);
    cudaMemsetAsync(rsum, 0, ROWS * sizeof(float));

    // 1) qkv = x @ W_qkv + b  (2-pass) -> hi everywhere; lo only for K cols
    gemm_mma<2,false,true,true,true,false,false><<<dim3(QKVD / 128, ROWS / 128, 1), 256, GSMEM>>>(
        x_h, DIM, 0, Wqkvt_h, Wqkvt_l, DIM, 0,
        nullptr, qkv_h, qkv_l, QKVD, 0, b_qkv, nullptr, DIM, 1.0f,
        DIM / 128, 2 * DIM / 128);   // lo n-blocks [6,12): K slice

    // 2) gw = softmax(q @ W_gp)  (q-hi only)
    gw_kernel2<<<ROWS / 64, 256>>>(qkv_h, W_gp, gw);

    // V^T per batch (hi plane only; ov GEMM is 1-pass)
    transpose_half<<<dim3(DIM / 32, SEQ / 32, BATCH), 256>>>(
        qkv_h + 2 * DIM, Vt_h, QKVD, SEQ, (long long)SEQ * QKVD, (long long)DIM * SEQ);

    // 3) S-GEMM (2-pass: Qh*(Kh+Kl)) -> exp fp16 + fused row sums
    gemm_mma<2,false,true,false,false,true,true><<<dim3(SEQ / 128, SEQ / 128, BATCH), 256, GSMEM>>>(
        qkv_h, QKVD, (long long)SEQ * QKVD,
        qkv_h + DIM, qkv_l + DIM, QKVD, (long long)SEQ * QKVD,
        nullptr, S_h, nullptr, SEQ, (long long)SEQ * SEQ, nullptr, rsum, DIM, scale, 0, 0);

    // 4) modulate in place
    modulate2<<<dim3(SEQ / 128, SEQ / 64, BATCH), 256>>>(S_h, gw, rsum, alpha);

    // 5) ov = W @ V  (1-pass: Wh*Vh) -> fp16 hi
    gemm_mma<1,false,true,false,false,false,false><<<dim3(DIM / 128, SEQ / 128, BATCH), 256, GSMEM>>>(
        S_h, SEQ, (long long)SEQ * SEQ,
        Vt_h, nullptr, SEQ, (long long)DIM * SEQ,
        nullptr, ov_h, nullptr, DIM, (long long)SEQ * DIM, nullptr, nullptr, SEQ, 1.0f, 0, 0);

    // 6) out = ov @ W_proj + b  (1-pass: ovh*Wh) -> fp32
    gemm_mma<1,true,false,false,true,false,false><<<dim3(DIM / 128, ROWS / 128, 1), 256, GSMEM>>>(
        ov_h, DIM, 0, Wprojt_h, nullptr, DIM, 0,
        out, nullptr, nullptr, DIM, 0, b_proj, nullptr, DIM, 1.0f, 0, 0);
}

// round 17
// speedup vs baseline: 1.4186x; 1.1401x over previous
#include <cuda_runtime.h>
#include <cuda_fp16.h>
#include <math.h>
#include <stdint.h>

#define BATCH 16
#define SEQ   1024
#define DIM   768
#define GP    49
#define ROWS  (BATCH * SEQ)      // 16384
#define QKVD  (3 * DIM)          // 2304

// ---------------- scratch (device globals) ----------------------------------
__device__ float g_gw [(size_t)ROWS * GP];
__device__ float g_rsum[ROWS];

__device__ half g_x_h   [(size_t)ROWS * DIM];
__device__ half g_qkv_h [(size_t)ROWS * QKVD];
__device__ half g_S_h   [(size_t)BATCH * SEQ * SEQ];
__device__ half g_Vt_h  [(size_t)BATCH * DIM * SEQ];
__device__ half g_ov_h  [(size_t)ROWS * DIM];
__device__ half g_Wqkvt_h [(size_t)QKVD * DIM];
__device__ half g_Wqkvt_l [(size_t)QKVD * DIM];
__device__ half g_Wprojt_h[(size_t)DIM * DIM];

// ============================ helpers =======================================
__device__ __forceinline__ uint32_t smem_u32(const void* p) {
    uint32_t a;
    asm("{ .reg .u64 t; cvta.to.shared.u64 t, %1; cvt.u32.u64 %0, t; }" : "=r"(a) : "l"(p));
    return a;
}
__device__ __forceinline__ void cp16(uint32_t s, const void* g) {
    asm volatile("cp.async.cg.shared.global [%0], [%1], 16;" :: "r"(s), "l"(g));
}
__device__ __forceinline__ void cp_commit() {
    asm volatile("cp.async.commit_group;" ::: "memory");
}
template<int N>
__device__ __forceinline__ void cp_wait() {
    asm volatile("cp.async.wait_group %0;" :: "n"(N) : "memory");
}
__device__ __forceinline__ void mma16816(float* d, const uint32_t* a, const uint32_t* b) {
    asm volatile(
        "mma.sync.aligned.m16n8k16.row.col.f32.f16.f16.f32 "
        "{%0,%1,%2,%3},{%4,%5,%6,%7},{%8,%9},{%0,%1,%2,%3};"
        : "+f"(d[0]), "+f"(d[1]), "+f"(d[2]), "+f"(d[3])
        : "r"(a[0]), "r"(a[1]), "r"(a[2]), "r"(a[3]), "r"(b[0]), "r"(b[1]));
}
__device__ __forceinline__ void ldmx4(uint32_t& r0, uint32_t& r1, uint32_t& r2, uint32_t& r3,
                                      uint32_t saddr) {
    asm volatile("ldmatrix.sync.aligned.m8n8.x4.shared.b16 {%0,%1,%2,%3}, [%4];"
                 : "=r"(r0), "=r"(r1), "=r"(r2), "=r"(r3) : "r"(saddr));
}
// swizzled byte offset within an 8KB plane (128 logical rows x 4 chunks of 16B)
__device__ __forceinline__ uint32_t swz(int row, int ch) {
    return (uint32_t)(((row >> 1) << 7) |
           (((((row & 1) << 2) + ch) ^ ((row >> 1) & 7)) << 4));
}

// ============ fp16-pair mma.sync GEMM: C = alpha*Ah*(Bh[+Bl]) (+bias) =======
// NPASS=2: Ah*(Bh+Bl); NPASS=1: Ah*Bh.
// R11 pipeline: 128x128 tile, 256 thr, K-chunk 32, 4-stage ring, depth 3.
// EXPH: store fp16(exp(C)); SUMEXP: fused per-row sum(exp) into rsum.
#define PLANE_B  8192u
#define STAGE_B  24576u
#define NSTAGE   4
#define GSMEM    (NSTAGE * STAGE_B)

template<int NPASS, bool WF32, bool WHI, bool BIAS, bool SUMEXP, bool EXPH>
__global__ void __launch_bounds__(256, 2) gemm_mma(
    const half* __restrict__ Ah, int lda, long long strA,
    const half* __restrict__ Bh, const half* __restrict__ Bl, int ldb, long long strB,
    float* __restrict__ C, half* __restrict__ Ch,
    int ldc, long long strC, const float* __restrict__ bias,
    float* __restrict__ rsum, int K, float alpha)
{
    extern __shared__ __align__(16) char smraw[];
    const uint32_t sb = smem_u32(smraw);
    const int tid  = threadIdx.x;
    const int lane = tid & 31;
    const int w    = tid >> 5;
    const int wm   = w & 1;
    const int wn   = w >> 1;
    const int m0 = blockIdx.y * 128, n0 = blockIdx.x * 128;

    const half* Abh = Ah + (long long)blockIdx.z * strA + (long long)m0 * lda;
    const half* Bbh = Bh + (long long)blockIdx.z * strB + (long long)n0 * ldb;
    const half* Bbl = (NPASS == 2) ? Bl + (long long)blockIdx.z * strB + (long long)n0 * ldb : nullptr;

    float acc[4][4][4];
#pragma unroll
    for (int i = 0; i < 4; i++)
#pragma unroll
        for (int j = 0; j < 4; j++)
#pragma unroll
            for (int r = 0; r < 4; r++) acc[i][j][r] = 0.f;

    const int nch = K >> 5;
    const int NCP = (NPASS == 2) ? 6 : 4;

    auto issue = [&](int k0, int stg) {
        const uint32_t base = sb + (uint32_t)stg * STAGE_B;
#pragma unroll
        for (int i = 0; i < NCP; i++) {
            const int plane = i >> 1;
            const int cid = ((i & 1) << 8) + tid;
            const int row = cid >> 2;
            const int ch  = cid & 3;
            const uint32_t so = base + (uint32_t)plane * PLANE_B + swz(row, ch);
            const half* gp;
            if      (plane == 0) gp = Abh + (long long)row * lda + k0 + ch * 8;
            else if (plane == 1) gp = Bbh + (long long)row * ldb + k0 + ch * 8;
            else                 gp = Bbl + (long long)row * ldb + k0 + ch * 8;
            cp16(so, gp);
        }
        cp_commit();
    };

    issue(0, 0);
    issue(32, 1);
    issue(64, 2);

    const int rowl = lane & 15;
    const int cb   = lane >> 4;

    for (int c = 0; c < nch; ++c) {
        const int st = c & (NSTAGE - 1);
        if      (c < nch - 2) cp_wait<2>();
        else if (c == nch - 2) cp_wait<1>();
        else                   cp_wait<0>();
        __syncthreads();
        if (c + 3 < nch) issue((c + 3) << 5, (c + 3) & (NSTAGE - 1));

        const uint32_t stA_h = sb + (uint32_t)st * STAGE_B;
        const uint32_t stB_h = stA_h + PLANE_B;
        const uint32_t stB_l = stA_h + 2 * PLANE_B;

#pragma unroll
        for (int ks = 0; ks < 2; ks++) {
            const int ch = 2 * ks + cb;
            uint32_t ah[4][4], bh[4][2];
#pragma unroll
            for (int mi = 0; mi < 4; mi++) {
                int row = wm * 64 + mi * 16 + rowl;
                ldmx4(ah[mi][0], ah[mi][1], ah[mi][2], ah[mi][3], stA_h + swz(row, ch));
            }
#pragma unroll
            for (int p = 0; p < 2; p++) {
                int row = wn * 32 + p * 16 + rowl;
                ldmx4(bh[2*p][0], bh[2*p+1][0], bh[2*p][1], bh[2*p+1][1], stB_h + swz(row, ch));
            }
#pragma unroll
            for (int mi = 0; mi < 4; mi++)
#pragma unroll
                for (int ni = 0; ni < 4; ni++)
                    mma16816(acc[mi][ni], ah[mi], bh[ni]);
            if (NPASS == 2) {
                uint32_t bl[4][2];
#pragma unroll
                for (int p = 0; p < 2; p++) {
                    int row = wn * 32 + p * 16 + rowl;
                    ldmx4(bl[2*p][0], bl[2*p+1][0], bl[2*p][1], bl[2*p+1][1], stB_l + swz(row, ch));
                }
#pragma unroll
                for (int mi = 0; mi < 4; mi++)
#pragma unroll
                    for (int ni = 0; ni < 4; ni++)
                        mma16816(acc[mi][ni], ah[mi], bl[ni]);
            }
        }
    }

    float* Cb  = WF32 ? C  + (long long)blockIdx.z * strC : nullptr;
    half*  Chb = WHI  ? Ch + (long long)blockIdx.z * strC : nullptr;
    float* rs  = SUMEXP ? rsum + blockIdx.z * SEQ : nullptr;
    const int r0 = m0 + wm * 64 + (lane >> 2);
    const int c0 = n0 + wn * 32 + ((lane & 3) << 1);
#pragma unroll
    for (int mi = 0; mi < 4; mi++) {
        float es[2] = {0.f, 0.f};
#pragma unroll
        for (int ni = 0; ni < 4; ni++) {
            int cc = c0 + ni * 8;
            float bx = 0.f, by = 0.f;
            if (BIAS) { bx = bias[cc]; by = bias[cc + 1]; }
#pragma unroll
            for (int h = 0; h < 2; h++) {
                int rr = r0 + mi * 16 + h * 8;
                float vx = acc[mi][ni][h * 2 + 0] * alpha + bx;
                float vy = acc[mi][ni][h * 2 + 1] * alpha + by;
                long long off = (long long)rr * ldc + cc;
                if (EXPH) {
                    float ex = expf(vx), ey = expf(vy);
                    if (SUMEXP) es[h] += ex + ey;
                    half2 hh;
                    hh.x = __float2half_rn(ex); hh.y = __float2half_rn(ey);
                    *(half2*)(Chb + off) = hh;
                } else {
                    if (WF32) *(float2*)(Cb + off) = make_float2(vx, vy);
                    if (WHI) {
                        half2 hh;
                        hh.x = __float2half_rn(vx); hh.y = __float2half_rn(vy);
                        *(half2*)(Chb + off) = hh;
                    }
                }
            }
        }
        if (SUMEXP) {
#pragma unroll
            for (int h = 0; h < 2; h++) {
                float v = es[h];
                v += __shfl_xor_sync(0xffffffffu, v, 1);
                v += __shfl_xor_sync(0xffffffffu, v, 2);
                if ((lane & 3) == 0)
                    atomicAdd(rs + r0 + mi * 16 + h * 8, v);
            }
        }
    }
}

// ================== fp32 -> fp16 hi-only ====================================
__global__ void __launch_bounds__(256) split_hi(
    const float* __restrict__ in, half* __restrict__ oh, size_t n)
{
    size_t i = ((size_t)blockIdx.x * 256 + threadIdx.x) * 4;
    if (i >= n) return;
    float4 v = *(const float4*)(in + i);
    half2 h0, h1;
    h0.x = __float2half_rn(v.x); h0.y = __float2half_rn(v.y);
    h1.x = __float2half_rn(v.z); h1.y = __float2half_rn(v.w);
    *(half2*)(oh + i) = h0; *(half2*)(oh + i + 2) = h1;
}

// ================== transpose + split fp32 -> fp16 pair =====================
__global__ void __launch_bounds__(256) transpose_split(
    const float* __restrict__ in, half* __restrict__ oh, half* __restrict__ ol,
    int ldin, int ldout, long long sIn, long long sOut)
{
    __shared__ float t[32][33];
    const float* ib = in + (long long)blockIdx.z * sIn;
    half* obh = oh + (long long)blockIdx.z * sOut;
    half* obl = ol + (long long)blockIdx.z * sOut;
    int r0 = blockIdx.y * 32, c0 = blockIdx.x * 32;
    int x = threadIdx.x & 31, y = threadIdx.x >> 5;
#pragma unroll
    for (int j = 0; j < 32; j += 8)
        t[y + j][x] = ib[(long long)(r0 + y + j) * ldin + c0 + x];
    __syncthreads();
#pragma unroll
    for (int j = 0; j < 32; j += 8) {
        float v = t[x][y + j];
        half h = __float2half_rn(v);
        long long o = (long long)(c0 + y + j) * ldout + r0 + x;
        obh[o] = h;
        if (ol) ol[o] = __float2half_rn(v - __half2float(h));
    }
}

// ======== transpose single half plane (V_h -> V^T_h) ========================
__global__ void __launch_bounds__(256) transpose_half(
    const half* __restrict__ in, half* __restrict__ out,
    int ldin, int ldout, long long sIn, long long sOut)
{
    __shared__ half t[32][34];
    const half* ib = in + (long long)blockIdx.z * sIn;
    half* ob = out + (long long)blockIdx.z * sOut;
    int r0 = blockIdx.y * 32, c0 = blockIdx.x * 32;
    int x = threadIdx.x & 31, y = threadIdx.x >> 5;
#pragma unroll
    for (int j = 0; j < 32; j += 8)
        t[y + j][x] = ib[(long long)(r0 + y + j) * ldin + c0 + x];
    __syncthreads();
#pragma unroll
    for (int j = 0; j < 32; j += 8)
        ob[(long long)(c0 + y + j) * ldout + r0 + x] = t[x][y + j];
}

// ------- gw = softmax(q @ W_gp), 64 rows / block, q-hi only ------------------
__global__ void __launch_bounds__(256) gw_kernel2(
    const half* __restrict__ qh,
    const float* __restrict__ Wgp, float* __restrict__ gw)
{
    __shared__ float wt[64][52];
    __shared__ float qt[64][65];
    __shared__ float lg[64][50];
    const int row0 = blockIdx.x * 64;
    const int tid = threadIdx.x;
    const int c  = tid & 63;
    const int rq = tid >> 6;

    float acc[16];
#pragma unroll
    for (int i = 0; i < 16; i++) acc[i] = 0.f;

    for (int kc = 0; kc < DIM / 64; kc++) {
        for (int idx = tid; idx < 64 * GP; idx += 256) {
            int kk = idx / GP, cc = idx - kk * GP;
            wt[kk][cc] = Wgp[(kc * 64 + kk) * GP + cc];
        }
        for (int idx = tid; idx < 4096; idx += 256) {
            int r = idx >> 6, kk = idx & 63;
            long long o = (long long)(row0 + r) * QKVD + kc * 64 + kk;
            qt[r][kk] = __half2float(qh[o]);
        }
        __syncthreads();
        if (c < GP) {
            for (int kk = 0; kk < 64; kk++) {
                float wv = wt[kk][c];
#pragma unroll
                for (int i = 0; i < 16; i++)
                    acc[i] = fmaf(qt[rq * 16 + i][kk], wv, acc[i]);
            }
        }
        __syncthreads();
    }
    if (c < GP)
#pragma unroll
        for (int i = 0; i < 16; i++) lg[rq * 16 + i][c] = acc[i];
    __syncthreads();
    if (tid < 64) {
        float m = lg[tid][0];
        for (int j = 1; j < GP; j++) m = fmaxf(m, lg[tid][j]);
        float s = 0.f;
        float e[GP];
        for (int j = 0; j < GP; j++) { e[j] = expf(lg[tid][j] - m); s += e[j]; }
        float inv = 1.f / s;
        for (int j = 0; j < GP; j++)
            gw[(long long)(row0 + tid) * GP + j] = e[j] * inv;
    }
}

// --- W = e/rsum * (a + (1-a)*<gw_i,gw_m>), in place; 4 rows x 2 cols/thread --
__global__ void __launch_bounds__(256) modulate3(
    half* __restrict__ Sh, const float* __restrict__ gw,
    const float* __restrict__ rsum, const float* __restrict__ alpha_p)
{
    __shared__ float gwm[128][51];
    const int b  = blockIdx.z;
    const int i0 = blockIdx.y * 64;
    const int m0 = blockIdx.x * 128;
    const int tid = threadIdx.x;

    for (int idx = tid; idx < 128 * GP; idx += 256) {
        int r = idx / GP, cc = idx - r * GP;
        gwm[r][cc] = gw[(long long)(b * SEQ + m0 + r) * GP + cc];
    }
    __syncthreads();

    const float a = 1.f / (1.f + expf(-alpha_p[0]));
    const float oma = 1.f - a;
    const int cw = tid & 63;      // half2 column index (cols 2cw, 2cw+1)
    const int rq = tid >> 6;      // 4 row lanes

    for (int ri = 0; ri < 4; ri++) {
        const int rbase = i0 + (ri * 4 + rq) * 4;   // 4 consecutive rows
        const int g0 = b * SEQ + rbase;
        const float* gp0 = gw + (long long)g0 * GP;
        float d[4][2];
#pragma unroll
        for (int rr = 0; rr < 4; rr++) { d[rr][0] = 0.f; d[rr][1] = 0.f; }
#pragma unroll
        for (int cc = 0; cc < GP; cc++) {
            float mv0 = gwm[2 * cw][cc];
            float mv1 = gwm[2 * cw + 1][cc];
#pragma unroll
            for (int rr = 0; rr < 4; rr++) {
                float g = __ldg(gp0 + (long long)rr * GP + cc);
                d[rr][0] = fmaf(g, mv0, d[rr][0]);
                d[rr][1] = fmaf(g, mv1, d[rr][1]);
            }
        }
#pragma unroll
        for (int rr = 0; rr < 4; rr++) {
            const int grow = g0 + rr;
            const float inv = 1.f / rsum[grow];
            half2* srow = (half2*)(Sh + (long long)grow * SEQ + m0);
            half2 e = srow[cw];
            float v0 = __half2float(e.x) * inv * (a + oma * d[rr][0]);
            float v1 = __half2float(e.y) * inv * (a + oma * d[rr][1]);
            half2 o; o.x = __float2half_rn(v0); o.y = __float2half_rn(v1);
            srow[cw] = o;
        }
    }
}

// ---------------- launcher ---------------------------------------------------
extern "C" void kernel_launch(void* const* d_in, const int* in_sizes, int n_in,
                              void* d_out, int out_size)
{
    const float* x      = (const float*)d_in[0];
    const float* W_qkv  = (const float*)d_in[1];
    const float* b_qkv  = (const float*)d_in[2];
    const float* W_proj = (const float*)d_in[3];
    const float* b_proj = (const float*)d_in[4];
    const float* W_gp   = (const float*)d_in[5];
    const float* alpha  = (const float*)d_in[6];
    float* out = (float*)d_out;

    float *gw, *rsum;
    half *x_h, *qkv_h, *S_h, *Vt_h, *ov_h;
    half *Wqkvt_h, *Wqkvt_l, *Wprojt_h;
    cudaGetSymbolAddress((void**)&gw,   g_gw);
    cudaGetSymbolAddress((void**)&rsum, g_rsum);
    cudaGetSymbolAddress((void**)&x_h,  g_x_h);
    cudaGetSymbolAddress((void**)&qkv_h, g_qkv_h);
    cudaGetSymbolAddress((void**)&S_h,  g_S_h);
    cudaGetSymbolAddress((void**)&Vt_h, g_Vt_h);
    cudaGetSymbolAddress((void**)&ov_h, g_ov_h);
    cudaGetSymbolAddress((void**)&Wqkvt_h,  g_Wqkvt_h);
    cudaGetSymbolAddress((void**)&Wqkvt_l,  g_Wqkvt_l);
    cudaGetSymbolAddress((void**)&Wprojt_h, g_Wprojt_h);

    const float scale = (float)(1.0 / sqrt((double)DIM));
    cudaFuncSetAttribute(gemm_mma<2,false,true,true,false,false>, cudaFuncAttributeMaxDynamicSharedMemorySize, GSMEM);
    cudaFuncSetAttribute(gemm_mma<1,false,true,false,true,true>,  cudaFuncAttributeMaxDynamicSharedMemorySize, GSMEM);
    cudaFuncSetAttribute(gemm_mma<1,false,true,false,false,false>,cudaFuncAttributeMaxDynamicSharedMemorySize, GSMEM);
    cudaFuncSetAttribute(gemm_mma<1,true,false,true,false,false>, cudaFuncAttributeMaxDynamicSharedMemorySize, GSMEM);

    split_hi<<<(ROWS * DIM) / 1024, 256>>>(x, x_h, (size_t)ROWS * DIM);
    transpose_split<<<dim3(QKVD / 32, DIM / 32, 1), 256>>>(W_qkv, Wqkvt_h, Wqkvt_l, QKVD, DIM, 0, 0);
    transpose_split<<<dim3(DIM / 32, DIM / 32, 1), 256>>>(W_proj, Wprojt_h, nullptr, DIM, DIM, 0, 0);
    cudaMemsetAsync(rsum, 0, ROWS * sizeof(float));

    // 1) qkv = x @ W_qkv + b  (2-pass over W) -> fp16 hi only
    gemm_mma<2,false,true,true,false,false><<<dim3(QKVD / 128, ROWS / 128, 1), 256, GSMEM>>>(
        x_h, DIM, 0, Wqkvt_h, Wqkvt_l, DIM, 0,
        nullptr, qkv_h, QKVD, 0, b_qkv, nullptr, DIM, 1.0f);

    // 2) gw = softmax(q @ W_gp)
    gw_kernel2<<<ROWS / 64, 256>>>(qkv_h, W_gp, gw);

    // V^T per batch (hi plane only)
    transpose_half<<<dim3(DIM / 32, SEQ / 32, BATCH), 256>>>(
        qkv_h + 2 * DIM, Vt_h, QKVD, SEQ, (long long)SEQ * QKVD, (long long)DIM * SEQ);

    // 3) S-GEMM (1-pass: Qh*Kh) -> exp fp16 + fused row sums
    gemm_mma<1,false,true,false,true,true><<<dim3(SEQ / 128, SEQ / 128, BATCH), 256, GSMEM>>>(
        qkv_h, QKVD, (long long)SEQ * QKVD,
        qkv_h + DIM, nullptr, QKVD, (long long)SEQ * QKVD,
        nullptr, S_h, SEQ, (long long)SEQ * SEQ, nullptr, rsum, DIM, scale);

    // 4) modulate in place (register-blocked)
    modulate3<<<dim3(SEQ / 128, SEQ / 64, BATCH), 256>>>(S_h, gw, rsum, alpha);

    // 5) ov = W @ V  (1-pass) -> fp16 hi
    gemm_mma<1,false,true,false,false,false><<<dim3(DIM / 128, SEQ / 128, BATCH), 256, GSMEM>>>(
        S_h, SEQ, (long long)SEQ * SEQ,
        Vt_h, nullptr, SEQ, (long long)DIM * SEQ,
        nullptr, ov_h, DIM, (long long)SEQ * DIM, nullptr, nullptr, SEQ, 1.0f);

    // 6) out = ov @ W_proj + b  (1-pass) -> fp32
    gemm_mma<1,true,false,true,false,false><<<dim3(DIM / 128, ROWS / 128, 1), 256, GSMEM>>>(
        ov_h, DIM, 0, Wprojt_h, nullptr, DIM, 0,
        out, nullptr, DIM, 0, b_proj, nullptr, DIM, 1.0f);
}